// round 10
// baseline (speedup 1.0000x reference)
#include <cuda_runtime.h>
#include <cuda_bf16.h>
#include <cstdint>
#include <cstddef>

// Problem constants
#define B_    4
#define N_    4096
#define M_    1024
#define QD_   1024
#define CD_   768
#define H_    16
#define D_    64
#define INNER 1024
#define BNQ   (B_ * N_)   // 16384 query rows
#define BMC   (B_ * M_)   // 4096 context rows

// ---------------------------------------------------------------------------
// Static device scratch
// ---------------------------------------------------------------------------
__device__ __nv_bfloat16 g_Qhi[BNQ * INNER], g_Qlo[BNQ * INNER];
__device__ __nv_bfloat16 g_Khi[BMC * INNER], g_Klo[BMC * INNER];
__device__ __nv_bfloat16 g_Vhi[BMC * INNER], g_Vlo[BMC * INNER];

__device__ __nv_bfloat16 g_xhi[BNQ * QD_],  g_xlo[BNQ * QD_];
__device__ __nv_bfloat16 g_chi[BMC * CD_],  g_clo[BMC * CD_];
__device__ __nv_bfloat16 g_WqThi[INNER * QD_], g_WqTlo[INNER * QD_];
__device__ __nv_bfloat16 g_WkThi[INNER * CD_], g_WkTlo[INNER * CD_];
__device__ __nv_bfloat16 g_WvThi[INNER * CD_], g_WvTlo[INNER * CD_];
__device__ __nv_bfloat16 g_WoThi[QD_ * INNER], g_WoTlo[QD_ * INNER];
__device__ __nv_bfloat16 g_AOhi[BNQ * INNER], g_AOlo[BNQ * INNER];

// ---------------------------------------------------------------------------
// PTX helpers (base sm_80/90 features only)
// ---------------------------------------------------------------------------
__device__ __forceinline__ uint32_t smem_u32(const void* p) {
    uint32_t a;
    asm("{ .reg .u64 t; cvta.to.shared.u64 t, %1; cvt.u32.u64 %0, t; }"
        : "=r"(a) : "l"(p));
    return a;
}

__device__ __forceinline__ void cp_async16(uint32_t dst, const void* src) {
    asm volatile("cp.async.cg.shared.global [%0], [%1], 16;"
                 :: "r"(dst), "l"(src) : "memory");
}
#define CP_COMMIT() asm volatile("cp.async.commit_group;" ::: "memory")
#define CP_WAIT(n)  asm volatile("cp.async.wait_group %0;" :: "n"(n) : "memory")

__device__ __forceinline__ void ldmatrix_x4(uint32_t& r0, uint32_t& r1,
                                            uint32_t& r2, uint32_t& r3, uint32_t a) {
    asm volatile("ldmatrix.sync.aligned.m8n8.x4.shared.b16 {%0,%1,%2,%3}, [%4];"
                 : "=r"(r0), "=r"(r1), "=r"(r2), "=r"(r3) : "r"(a));
}

__device__ __forceinline__ void ldmatrix_x4_t(uint32_t& r0, uint32_t& r1,
                                              uint32_t& r2, uint32_t& r3, uint32_t a) {
    asm volatile("ldmatrix.sync.aligned.m8n8.x4.trans.shared.b16 {%0,%1,%2,%3}, [%4];"
                 : "=r"(r0), "=r"(r1), "=r"(r2), "=r"(r3) : "r"(a));
}

__device__ __forceinline__ void mma16816(float* d, const uint32_t* a,
                                         const uint32_t* b) {
    asm volatile(
        "mma.sync.aligned.m16n8k16.row.col.f32.bf16.bf16.f32 "
        "{%0,%1,%2,%3}, {%4,%5,%6,%7}, {%8,%9}, {%0,%1,%2,%3};"
        : "+f"(d[0]), "+f"(d[1]), "+f"(d[2]), "+f"(d[3])
        : "r"(a[0]), "r"(a[1]), "r"(a[2]), "r"(a[3]), "r"(b[0]), "r"(b[1]));
}

// Truncation hi/lo split, packed as bf16x2 (element0 = low half = v0)
__device__ __forceinline__ uint32_t pack_hi2(float v0, float v1) {
    return __byte_perm(__float_as_uint(v0), __float_as_uint(v1), 0x7632);
}
__device__ __forceinline__ uint32_t pack_lo2(float v0, float v1) {
    float l0 = v0 - __uint_as_float(__float_as_uint(v0) & 0xffff0000u);
    float l1 = v1 - __uint_as_float(__float_as_uint(v1) & 0xffff0000u);
    uint32_t r;
    asm("cvt.rn.bf16x2.f32 %0, %1, %2;" : "=r"(r) : "f"(l1), "f"(l0));
    return r;
}

// ---------------------------------------------------------------------------
// Conversion kernels: fp32 -> (hi, lo) bf16 split
// ---------------------------------------------------------------------------
__global__ void cvt_hilo_kernel(const float* __restrict__ in,
                                __nv_bfloat16* __restrict__ hi,
                                __nv_bfloat16* __restrict__ lo, int n4)
{
    int i = blockIdx.x * blockDim.x + threadIdx.x;
    if (i >= n4) return;
    float4 v = reinterpret_cast<const float4*>(in)[i];
    reinterpret_cast<uint32_t*>(hi)[i * 2 + 0] = pack_hi2(v.x, v.y);
    reinterpret_cast<uint32_t*>(hi)[i * 2 + 1] = pack_hi2(v.z, v.w);
    reinterpret_cast<uint32_t*>(lo)[i * 2 + 0] = pack_lo2(v.x, v.y);
    reinterpret_cast<uint32_t*>(lo)[i * 2 + 1] = pack_lo2(v.z, v.w);
}

// W [K,N] row-major  ->  T [N,K] (hi, lo) bf16
__global__ void transpose_cvt_kernel(const float* __restrict__ W,
                                     __nv_bfloat16* __restrict__ Thi,
                                     __nv_bfloat16* __restrict__ Tlo, int K, int N)
{
    __shared__ float t[32][33];
    int tx = threadIdx.x, ty = threadIdx.y;          // 32 x 8
    int n0 = blockIdx.x * 32, k0 = blockIdx.y * 32;
    #pragma unroll
    for (int j = 0; j < 4; ++j)
        t[ty + j * 8][tx] = W[(size_t)(k0 + ty + j * 8) * N + n0 + tx];
    __syncthreads();
    #pragma unroll
    for (int j = 0; j < 4; ++j) {
        float v = t[tx][ty + j * 8];
        int n = n0 + ty + j * 8, k = k0 + tx;
        uint32_t u = __float_as_uint(v);
        float hv = __uint_as_float(u & 0xffff0000u);
        Thi[(size_t)n * K + k] = __ushort_as_bfloat16((unsigned short)(u >> 16));
        Tlo[(size_t)n * K + k] = __float2bfloat16(v - hv);
    }
}

// ---------------------------------------------------------------------------
// mma.sync GEMM: C = A @ B^T (B stored [N,K] K-major), split-bf16 x3.
// 128 threads, 4 warps in 2x2, warp tile 64x64 (maximizes smem-read reuse:
// each LDSM-ed fragment feeds 2x more HMMA than the old 64x32 warp tile).
// 2-stage cp.async pipeline (distance 1), ONE barrier per K-chunk.
// BF16OUT: write (hi, lo) bf16 with scale folded; else fp32 (+bias).
// ---------------------------------------------------------------------------
#define SA_        72
#define TILE_B     (128 * SA_ * 2)
#define OFF_AHI    0
#define OFF_ALO    (TILE_B)
#define OFF_BHI    (2 * TILE_B)
#define OFF_BLO    (3 * TILE_B)
#define BUF_B      (4 * TILE_B)             // 73728 per stage
#define GEMM_SMEM  (2 * BUF_B)              // 147456 (proven envelope)

template <bool BF16OUT>
__global__ __launch_bounds__(128) void mma_gemm_kernel(
    const __nv_bfloat16* __restrict__ Ahi, const __nv_bfloat16* __restrict__ Alo,
    const __nv_bfloat16* __restrict__ Bhi, const __nv_bfloat16* __restrict__ Blo,
    float* __restrict__ C, __nv_bfloat16* __restrict__ Chi,
    __nv_bfloat16* __restrict__ Clo, float scale,
    int Ndim, int Kdim, const float* __restrict__ bias)
{
    extern __shared__ __align__(128) char smem[];
    const uint32_t sb = smem_u32(smem);
    const int tid = threadIdx.x, wid = tid >> 5, l = tid & 31;
    const int warp_m = wid >> 1, warp_n = wid & 1;
    const int brow = blockIdx.y * 128, bcol = blockIdx.x * 128;

    const int a_row = warp_m * 64 + (l & 7) + ((l >> 3) & 1) * 8;
    const int a_col = ((l >> 4) & 1) * 8;
    const int b_row = warp_n * 64 + (l & 7) + ((l >> 4) & 1) * 8;
    const int b_col = ((l >> 3) & 1) * 8;
    const uint32_t aOff = (uint32_t)(a_row * SA_ + a_col) * 2;
    const uint32_t bOff = (uint32_t)(b_row * SA_ + b_col) * 2;

    float acc[4][8][4];
    #pragma unroll
    for (int im = 0; im < 4; ++im)
        #pragma unroll
        for (int j = 0; j < 8; ++j)
            #pragma unroll
            for (int q = 0; q < 4; ++q) acc[im][j][q] = 0.f;

    const int nch = Kdim >> 6;

    auto stage = [&](int ch, int bb) {
        const int k0 = ch << 6;
        const uint32_t base = sb + (uint32_t)bb * BUF_B;
        #pragma unroll
        for (int i = 0; i < 8; ++i) {
            int s = tid + i * 128;           // 0..1023
            int r = s >> 3, c = s & 7;
            uint32_t so = (uint32_t)(r * 144 + c * 16);
            size_t ga = (size_t)(brow + r) * Kdim + k0 + c * 8;
            size_t gb = (size_t)(bcol + r) * Kdim + k0 + c * 8;
            cp_async16(base + OFF_AHI + so, Ahi + ga);
            cp_async16(base + OFF_ALO + so, Alo + ga);
            cp_async16(base + OFF_BHI + so, Bhi + gb);
            cp_async16(base + OFF_BLO + so, Blo + gb);
        }
        CP_COMMIT();
    };

    stage(0, 0);

    for (int ch = 0; ch < nch; ++ch) {
        CP_WAIT(0);
        __syncthreads();
        // stage(ch+1) writes buffer (ch+1)%2; compute below reads ch%2.
        if (ch + 1 < nch) stage(ch + 1, (ch + 1) & 1);

        const uint32_t base = sb + (uint32_t)(ch & 1) * BUF_B;
        #pragma unroll
        for (int ks = 0; ks < 4; ++ks) {
            uint32_t ahi[4][4], alo[4][4], bhi[8][2], blo[8][2];
            #pragma unroll
            for (int im = 0; im < 4; ++im) {
                uint32_t ao = aOff + (uint32_t)(im * 16 * SA_ + ks * 16) * 2;
                ldmatrix_x4(ahi[im][0], ahi[im][1], ahi[im][2], ahi[im][3],
                            base + OFF_AHI + ao);
                ldmatrix_x4(alo[im][0], alo[im][1], alo[im][2], alo[im][3],
                            base + OFF_ALO + ao);
            }
            #pragma unroll
            for (int in16 = 0; in16 < 4; ++in16) {
                uint32_t bo = bOff + (uint32_t)(in16 * 16 * SA_ + ks * 16) * 2;
                ldmatrix_x4(bhi[in16 * 2][0], bhi[in16 * 2][1],
                            bhi[in16 * 2 + 1][0], bhi[in16 * 2 + 1][1],
                            base + OFF_BHI + bo);
                ldmatrix_x4(blo[in16 * 2][0], blo[in16 * 2][1],
                            blo[in16 * 2 + 1][0], blo[in16 * 2 + 1][1],
                            base + OFF_BLO + bo);
            }
            #pragma unroll
            for (int im = 0; im < 4; ++im)
                #pragma unroll
                for (int j = 0; j < 8; ++j) {
                    mma16816(acc[im][j], ahi[im], bhi[j]);
                    mma16816(acc[im][j], ahi[im], blo[j]);
                    mma16816(acc[im][j], alo[im], bhi[j]);
                }
        }
    }

    #pragma unroll
    for (int im = 0; im < 4; ++im) {
        int row = brow + warp_m * 64 + im * 16 + (l >> 2);
        #pragma unroll
        for (int j = 0; j < 8; ++j) {
            int col = bcol + warp_n * 64 + j * 8 + (l & 3) * 2;
            if (BF16OUT) {
                float v0 = acc[im][j][0] * scale, v1 = acc[im][j][1] * scale;
                float v2 = acc[im][j][2] * scale, v3 = acc[im][j][3] * scale;
                size_t o0 = (size_t)row * Ndim + col;
                size_t o1 = (size_t)(row + 8) * Ndim + col;
                *reinterpret_cast<uint32_t*>(Chi + o0) = pack_hi2(v0, v1);
                *reinterpret_cast<uint32_t*>(Clo + o0) = pack_lo2(v0, v1);
                *reinterpret_cast<uint32_t*>(Chi + o1) = pack_hi2(v2, v3);
                *reinterpret_cast<uint32_t*>(Clo + o1) = pack_lo2(v2, v3);
            } else {
                float2 v0 = {acc[im][j][0], acc[im][j][1]};
                float2 v1 = {acc[im][j][2], acc[im][j][3]};
                if (bias) {
                    float2 bv = *reinterpret_cast<const float2*>(bias + col);
                    v0.x += bv.x; v0.y += bv.y; v1.x += bv.x; v1.y += bv.y;
                }
                *reinterpret_cast<float2*>(C + (size_t)row * Ndim + col) = v0;
                *reinterpret_cast<float2*>(C + (size_t)(row + 8) * Ndim + col) = v1;
            }
        }
    }
}

// ---------------------------------------------------------------------------
// FA2-style attention, mma.sync, split-bf16 x3 on both matmuls.
// CTA = (b, h, 128 q rows); 8 warps x 16 rows; kv tile = 64, 2-stage pipeline
// (distance 1), ONE barrier per tile. smem/stage: Khi|Klo|Vhi|Vlo (64x72 bf16).
// ---------------------------------------------------------------------------
#define AT_STG    36864
#define AT_SMEM   (2 * AT_STG)              // 73728 (proven envelope)
#define AT_KLO    9216
#define AT_VHI    18432
#define AT_VLO    27648

__global__ __launch_bounds__(256) void attn_mma_kernel(
    const __nv_bfloat16* __restrict__ Qhi, const __nv_bfloat16* __restrict__ Qlo,
    const __nv_bfloat16* __restrict__ Khi, const __nv_bfloat16* __restrict__ Klo,
    const __nv_bfloat16* __restrict__ Vhi, const __nv_bfloat16* __restrict__ Vlo,
    __nv_bfloat16* __restrict__ AOhi, __nv_bfloat16* __restrict__ AOlo)
{
    extern __shared__ __align__(128) char smem[];
    const uint32_t sb = smem_u32(smem);
    const int tid = threadIdx.x, wid = tid >> 5, l = tid & 31;
    const int b = blockIdx.z, h = blockIdx.y;
    const int q0 = blockIdx.x * 128;
    const size_t qrow0 = (size_t)(b * N_ + q0);
    const size_t krow0 = (size_t)(b * M_);
    const int hc = h * 64;

    // ---- Stage Q tile (128 x 64 hi/lo) into stage-0 region, build A frags
    #pragma unroll
    for (int i = 0; i < 4; ++i) {
        int s = tid + i * 256;               // 0..1023
        int r = s >> 3, c = s & 7;
        uint32_t so = (uint32_t)(r * 144 + c * 16);
        size_t g = (qrow0 + r) * INNER + hc + c * 8;
        cp_async16(sb + so, Qhi + g);
        cp_async16(sb + 18432 + so, Qlo + g);
    }
    CP_COMMIT(); CP_WAIT(0);
    __syncthreads();

    uint32_t qh[4][4], ql[4][4];
    {
        int ar = wid * 16 + (l & 7) + ((l >> 3) & 1) * 8;
        int ac = ((l >> 4) & 1) * 8;
        #pragma unroll
        for (int ks = 0; ks < 4; ++ks) {
            uint32_t ad = sb + (uint32_t)(ar * SA_ + ac + ks * 16) * 2;
            ldmatrix_x4(qh[ks][0], qh[ks][1], qh[ks][2], qh[ks][3], ad);
            ldmatrix_x4(ql[ks][0], ql[ks][1], ql[ks][2], ql[ks][3], ad + 18432);
        }
    }
    __syncthreads();

    float o[8][4];
    #pragma unroll
    for (int j = 0; j < 8; ++j)
        #pragma unroll
        for (int q = 0; q < 4; ++q) o[j][q] = 0.f;
    float m0 = -1e30f, m1 = -1e30f, lp0 = 0.f, lp1 = 0.f;

    auto stageKV = [&](int t, int bb) {
        const uint32_t base = sb + (uint32_t)bb * AT_STG;
        const int kv0 = t * 64;
        #pragma unroll
        for (int i = 0; i < 2; ++i) {
            int s = tid + i * 256;           // 0..511
            int r = s >> 3, c = s & 7;
            uint32_t so = (uint32_t)(r * 144 + c * 16);
            size_t g = (krow0 + kv0 + r) * INNER + hc + c * 8;
            cp_async16(base + so,          Khi + g);
            cp_async16(base + AT_KLO + so, Klo + g);
            cp_async16(base + AT_VHI + so, Vhi + g);
            cp_async16(base + AT_VLO + so, Vlo + g);
        }
        CP_COMMIT();
    };

    stageKV(0, 0);

    const int nr  = (l & 7) + ((l >> 4) & 1) * 8;    // K-frag row in tile
    const int kc8 = ((l >> 3) & 1) * 8;              // K-frag col offset
    const int vg  = l >> 3, vi = l & 7;              // V trans-frag coords
    const int NT  = M_ / 64;

    for (int t = 0; t < NT; ++t) {
        CP_WAIT(0);
        __syncthreads();
        if (t + 1 < NT) stageKV(t + 1, (t + 1) & 1);
        const uint32_t kb = sb + (uint32_t)(t & 1) * AT_STG;

        // ---- S = Q K^T (3 split products)
        float s[8][4];
        #pragma unroll
        for (int j = 0; j < 8; ++j)
            #pragma unroll
            for (int q = 0; q < 4; ++q) s[j][q] = 0.f;

        #pragma unroll
        for (int ks = 0; ks < 4; ++ks) {
            #pragma unroll
            for (int jn = 0; jn < 4; ++jn) {
                uint32_t ad = kb + (uint32_t)((jn * 16 + nr) * SA_ + ks * 16 + kc8) * 2;
                uint32_t h0, h1, h2, h3, l0, l1, l2, l3;
                ldmatrix_x4(h0, h1, h2, h3, ad);
                ldmatrix_x4(l0, l1, l2, l3, ad + AT_KLO);
                uint32_t bh0[2] = {h0, h1}, bh1[2] = {h2, h3};
                uint32_t bl0[2] = {l0, l1}, bl1[2] = {l2, l3};
                mma16816(s[2 * jn],     qh[ks], bh0);
                mma16816(s[2 * jn],     qh[ks], bl0);
                mma16816(s[2 * jn],     ql[ks], bh0);
                mma16816(s[2 * jn + 1], qh[ks], bh1);
                mma16816(s[2 * jn + 1], qh[ks], bl1);
                mma16816(s[2 * jn + 1], ql[ks], bh1);
            }
        }

        // ---- online softmax (rows r = l/4 and r+8)
        float mx0 = -1e30f, mx1 = -1e30f;
        #pragma unroll
        for (int j = 0; j < 8; ++j) {
            mx0 = fmaxf(mx0, fmaxf(s[j][0], s[j][1]));
            mx1 = fmaxf(mx1, fmaxf(s[j][2], s[j][3]));
        }
        mx0 = fmaxf(mx0, __shfl_xor_sync(0xffffffffu, mx0, 1));
        mx0 = fmaxf(mx0, __shfl_xor_sync(0xffffffffu, mx0, 2));
        mx1 = fmaxf(mx1, __shfl_xor_sync(0xffffffffu, mx1, 1));
        mx1 = fmaxf(mx1, __shfl_xor_sync(0xffffffffu, mx1, 2));

        float nm0 = fmaxf(m0, mx0), nm1 = fmaxf(m1, mx1);
        float al0 = __expf(m0 - nm0), al1 = __expf(m1 - nm1);
        m0 = nm0; m1 = nm1;

        float add0 = 0.f, add1 = 0.f;
        #pragma unroll
        for (int j = 0; j < 8; ++j) {
            s[j][0] = __expf(s[j][0] - nm0);
            s[j][1] = __expf(s[j][1] - nm0);
            s[j][2] = __expf(s[j][2] - nm1);
            s[j][3] = __expf(s[j][3] - nm1);
            add0 += s[j][0] + s[j][1];
            add1 += s[j][2] + s[j][3];
        }
        lp0 = lp0 * al0 + add0;
        lp1 = lp1 * al1 + add1;
        #pragma unroll
        for (int j = 0; j < 8; ++j) {
            o[j][0] *= al0; o[j][1] *= al0;
            o[j][2] *= al1; o[j][3] *= al1;
        }

        // ---- AV (3 split products), P frags built from s in-registers
        #pragma unroll
        for (int t2 = 0; t2 < 4; ++t2) {
            uint32_t pah[4], pal[4];
            pah[0] = pack_hi2(s[2 * t2][0],     s[2 * t2][1]);
            pah[1] = pack_hi2(s[2 * t2][2],     s[2 * t2][3]);
            pah[2] = pack_hi2(s[2 * t2 + 1][0], s[2 * t2 + 1][1]);
            pah[3] = pack_hi2(s[2 * t2 + 1][2], s[2 * t2 + 1][3]);
            pal[0] = pack_lo2(s[2 * t2][0],     s[2 * t2][1]);
            pal[1] = pack_lo2(s[2 * t2][2],     s[2 * t2][3]);
            pal[2] = pack_lo2(s[2 * t2 + 1][0], s[2 * t2 + 1][1]);
            pal[3] = pack_lo2(s[2 * t2 + 1][2], s[2 * t2 + 1][3]);

            #pragma unroll
            for (int jn = 0; jn < 4; ++jn) {
                uint32_t ad = kb + AT_VHI +
                    (uint32_t)((t2 * 16 + (vg & 1) * 8 + vi) * SA_ +
                               jn * 16 + (vg >> 1) * 8) * 2;
                uint32_t h0, h1, h2, h3, l0, l1, l2, l3;
                ldmatrix_x4_t(h0, h1, h2, h3, ad);
                ldmatrix_x4_t(l0, l1, l2, l3, ad + (AT_VLO - AT_VHI));
                uint32_t bh0[2] = {h0, h1}, bh1[2] = {h2, h3};
                uint32_t bl0[2] = {l0, l1}, bl1[2] = {l2, l3};
                mma16816(o[2 * jn],     pah, bh0);
                mma16816(o[2 * jn],     pah, bl0);
                mma16816(o[2 * jn],     pal, bh0);
                mma16816(o[2 * jn + 1], pah, bh1);
                mma16816(o[2 * jn + 1], pah, bl1);
                mma16816(o[2 * jn + 1], pal, bh1);
            }
        }
    }

    // ---- normalize + write hi/lo bf16
    lp0 += __shfl_xor_sync(0xffffffffu, lp0, 1);
    lp0 += __shfl_xor_sync(0xffffffffu, lp0, 2);
    lp1 += __shfl_xor_sync(0xffffffffu, lp1, 1);
    lp1 += __shfl_xor_sync(0xffffffffu, lp1, 2);
    float inv0 = 1.f / lp0, inv1 = 1.f / lp1;

    size_t r0g = (qrow0 + wid * 16 + (l >> 2)) * INNER + hc;
    size_t r1g = r0g + (size_t)8 * INNER;
    #pragma unroll
    for (int j = 0; j < 8; ++j) {
        int c = j * 8 + (l & 3) * 2;
        float v0 = o[j][0] * inv0, v1 = o[j][1] * inv0;
        float v2 = o[j][2] * inv1, v3 = o[j][3] * inv1;
        *reinterpret_cast<uint32_t*>(AOhi + r0g + c) = pack_hi2(v0, v1);
        *reinterpret_cast<uint32_t*>(AOlo + r0g + c) = pack_lo2(v0, v1);
        *reinterpret_cast<uint32_t*>(AOhi + r1g + c) = pack_hi2(v2, v3);
        *reinterpret_cast<uint32_t*>(AOlo + r1g + c) = pack_lo2(v2, v3);
    }
}

// ---------------------------------------------------------------------------
// Launch
// ---------------------------------------------------------------------------
extern "C" void kernel_launch(void* const* d_in, const int* in_sizes, int n_in,
                              void* d_out, int out_size)
{
    const float* x   = (const float*)d_in[0];
    const float* ctx = (const float*)d_in[1];
    const float* Wq  = (const float*)d_in[2];
    const float* Wk  = (const float*)d_in[3];
    const float* Wv  = (const float*)d_in[4];
    const float* Wo  = (const float*)d_in[5];
    const float* bo  = (const float*)d_in[6];
    float* out = (float*)d_out;

    cudaFuncSetAttribute(mma_gemm_kernel<true>,
                         cudaFuncAttributeMaxDynamicSharedMemorySize, GEMM_SMEM);
    cudaFuncSetAttribute(mma_gemm_kernel<false>,
                         cudaFuncAttributeMaxDynamicSharedMemorySize, GEMM_SMEM);
    cudaFuncSetAttribute(attn_mma_kernel,
                         cudaFuncAttributeMaxDynamicSharedMemorySize, AT_SMEM);

    __nv_bfloat16 *qhi, *qlo, *khi, *klo, *vhi, *vlo;
    __nv_bfloat16 *xhi, *xlo, *chi, *clo, *aohi, *aolo;
    __nv_bfloat16 *wqh, *wql, *wkh, *wkl, *wvh, *wvl, *woh, *wol;
    cudaGetSymbolAddress((void**)&qhi, g_Qhi);  cudaGetSymbolAddress((void**)&qlo, g_Qlo);
    cudaGetSymbolAddress((void**)&khi, g_Khi);  cudaGetSymbolAddress((void**)&klo, g_Klo);
    cudaGetSymbolAddress((void**)&vhi, g_Vhi);  cudaGetSymbolAddress((void**)&vlo, g_Vlo);
    cudaGetSymbolAddress((void**)&xhi, g_xhi);  cudaGetSymbolAddress((void**)&xlo, g_xlo);
    cudaGetSymbolAddress((void**)&chi, g_chi);  cudaGetSymbolAddress((void**)&clo, g_clo);
    cudaGetSymbolAddress((void**)&aohi, g_AOhi); cudaGetSymbolAddress((void**)&aolo, g_AOlo);
    cudaGetSymbolAddress((void**)&wqh, g_WqThi); cudaGetSymbolAddress((void**)&wql, g_WqTlo);
    cudaGetSymbolAddress((void**)&wkh, g_WkThi); cudaGetSymbolAddress((void**)&wkl, g_WkTlo);
    cudaGetSymbolAddress((void**)&wvh, g_WvThi); cudaGetSymbolAddress((void**)&wvl, g_WvTlo);
    cudaGetSymbolAddress((void**)&woh, g_WoThi); cudaGetSymbolAddress((void**)&wol, g_WoTlo);

    // 1. Split-convert inputs
    {
        int n4 = (BNQ * QD_) / 4;
        cvt_hilo_kernel<<<n4 / 256, 256>>>(x, xhi, xlo, n4);
        n4 = (BMC * CD_) / 4;
        cvt_hilo_kernel<<<n4 / 256, 256>>>(ctx, chi, clo, n4);
    }
    transpose_cvt_kernel<<<dim3(INNER / 32, QD_ / 32), dim3(32, 8)>>>(Wq, wqh, wql, QD_, INNER);
    transpose_cvt_kernel<<<dim3(INNER / 32, CD_ / 32), dim3(32, 8)>>>(Wk, wkh, wkl, CD_, INNER);
    transpose_cvt_kernel<<<dim3(INNER / 32, CD_ / 32), dim3(32, 8)>>>(Wv, wvh, wvl, CD_, INNER);
    transpose_cvt_kernel<<<dim3(QD_ / 32, INNER / 32), dim3(32, 8)>>>(Wo, woh, wol, INNER, QD_);

    // 2. Projections -> hi/lo bf16 (Q with softmax scale folded in)
    mma_gemm_kernel<true><<<dim3(INNER / 128, BNQ / 128), 128, GEMM_SMEM>>>(
        xhi, xlo, wqh, wql, nullptr, qhi, qlo, 0.125f, INNER, QD_, nullptr);
    mma_gemm_kernel<true><<<dim3(INNER / 128, BMC / 128), 128, GEMM_SMEM>>>(
        chi, clo, wkh, wkl, nullptr, khi, klo, 1.0f, INNER, CD_, nullptr);
    mma_gemm_kernel<true><<<dim3(INNER / 128, BMC / 128), 128, GEMM_SMEM>>>(
        chi, clo, wvh, wvl, nullptr, vhi, vlo, 1.0f, INNER, CD_, nullptr);

    // 3. Attention (tensor-core FA2)
    attn_mma_kernel<<<dim3(N_ / 128, H_, B_), 256, AT_SMEM>>>(
        qhi, qlo, khi, klo, vhi, vlo, aohi, aolo);

    // 4. Output projection + bias -> d_out (fp32)
    mma_gemm_kernel<false><<<dim3(QD_ / 128, BNQ / 128), 128, GEMM_SMEM>>>(
        aohi, aolo, woh, wol, out, nullptr, nullptr, 1.0f, QD_, INNER, bo);
}

// round 12
// speedup vs baseline: 1.0326x; 1.0326x over previous
#include <cuda_runtime.h>
#include <cuda_bf16.h>
#include <cstdint>
#include <cstddef>

// Problem constants
#define B_    4
#define N_    4096
#define M_    1024
#define QD_   1024
#define CD_   768
#define H_    16
#define D_    64
#define INNER 1024
#define BNQ   (B_ * N_)   // 16384 query rows
#define BMC   (B_ * M_)   // 4096 context rows

// ---------------------------------------------------------------------------
// Static device scratch
// ---------------------------------------------------------------------------
__device__ __nv_bfloat16 g_Qhi[BNQ * INNER], g_Qlo[BNQ * INNER];
__device__ __nv_bfloat16 g_Khi[BMC * INNER], g_Klo[BMC * INNER];
__device__ __nv_bfloat16 g_Vhi[BMC * INNER], g_Vlo[BMC * INNER];

__device__ __nv_bfloat16 g_xhi[BNQ * QD_],  g_xlo[BNQ * QD_];
__device__ __nv_bfloat16 g_chi[BMC * CD_],  g_clo[BMC * CD_];
__device__ __nv_bfloat16 g_WqThi[INNER * QD_], g_WqTlo[INNER * QD_];
__device__ __nv_bfloat16 g_WkThi[INNER * CD_], g_WkTlo[INNER * CD_];
__device__ __nv_bfloat16 g_WvThi[INNER * CD_], g_WvTlo[INNER * CD_];
__device__ __nv_bfloat16 g_WoThi[QD_ * INNER], g_WoTlo[QD_ * INNER];
__device__ __nv_bfloat16 g_AOhi[BNQ * INNER], g_AOlo[BNQ * INNER];

// ---------------------------------------------------------------------------
// PTX helpers (base sm_80/90 features only)
// ---------------------------------------------------------------------------
__device__ __forceinline__ uint32_t smem_u32(const void* p) {
    uint32_t a;
    asm("{ .reg .u64 t; cvta.to.shared.u64 t, %1; cvt.u32.u64 %0, t; }"
        : "=r"(a) : "l"(p));
    return a;
}

__device__ __forceinline__ void cp_async16(uint32_t dst, const void* src) {
    asm volatile("cp.async.cg.shared.global [%0], [%1], 16;"
                 :: "r"(dst), "l"(src) : "memory");
}
#define CP_COMMIT() asm volatile("cp.async.commit_group;" ::: "memory")
#define CP_WAIT(n)  asm volatile("cp.async.wait_group %0;" :: "n"(n) : "memory")

__device__ __forceinline__ void ldmatrix_x4(uint32_t& r0, uint32_t& r1,
                                            uint32_t& r2, uint32_t& r3, uint32_t a) {
    asm volatile("ldmatrix.sync.aligned.m8n8.x4.shared.b16 {%0,%1,%2,%3}, [%4];"
                 : "=r"(r0), "=r"(r1), "=r"(r2), "=r"(r3) : "r"(a));
}

__device__ __forceinline__ void ldmatrix_x4_t(uint32_t& r0, uint32_t& r1,
                                              uint32_t& r2, uint32_t& r3, uint32_t a) {
    asm volatile("ldmatrix.sync.aligned.m8n8.x4.trans.shared.b16 {%0,%1,%2,%3}, [%4];"
                 : "=r"(r0), "=r"(r1), "=r"(r2), "=r"(r3) : "r"(a));
}

__device__ __forceinline__ void mma16816(float* d, const uint32_t* a,
                                         const uint32_t* b) {
    asm volatile(
        "mma.sync.aligned.m16n8k16.row.col.f32.bf16.bf16.f32 "
        "{%0,%1,%2,%3}, {%4,%5,%6,%7}, {%8,%9}, {%0,%1,%2,%3};"
        : "+f"(d[0]), "+f"(d[1]), "+f"(d[2]), "+f"(d[3])
        : "r"(a[0]), "r"(a[1]), "r"(a[2]), "r"(a[3]), "r"(b[0]), "r"(b[1]));
}

// Truncation hi/lo split, packed as bf16x2 (element0 = low half = v0)
__device__ __forceinline__ uint32_t pack_hi2(float v0, float v1) {
    return __byte_perm(__float_as_uint(v0), __float_as_uint(v1), 0x7632);
}
__device__ __forceinline__ uint32_t pack_lo2(float v0, float v1) {
    float l0 = v0 - __uint_as_float(__float_as_uint(v0) & 0xffff0000u);
    float l1 = v1 - __uint_as_float(__float_as_uint(v1) & 0xffff0000u);
    uint32_t r;
    asm("cvt.rn.bf16x2.f32 %0, %1, %2;" : "=r"(r) : "f"(l1), "f"(l0));
    return r;
}

// ---------------------------------------------------------------------------
// Conversion kernels: fp32 -> (hi, lo) bf16 split
// ---------------------------------------------------------------------------
__global__ void cvt_hilo_kernel(const float* __restrict__ in,
                                __nv_bfloat16* __restrict__ hi,
                                __nv_bfloat16* __restrict__ lo, int n4)
{
    int i = blockIdx.x * blockDim.x + threadIdx.x;
    if (i >= n4) return;
    float4 v = reinterpret_cast<const float4*>(in)[i];
    reinterpret_cast<uint32_t*>(hi)[i * 2 + 0] = pack_hi2(v.x, v.y);
    reinterpret_cast<uint32_t*>(hi)[i * 2 + 1] = pack_hi2(v.z, v.w);
    reinterpret_cast<uint32_t*>(lo)[i * 2 + 0] = pack_lo2(v.x, v.y);
    reinterpret_cast<uint32_t*>(lo)[i * 2 + 1] = pack_lo2(v.z, v.w);
}

// W [K,N] row-major  ->  T [N,K] (hi, lo) bf16
__global__ void transpose_cvt_kernel(const float* __restrict__ W,
                                     __nv_bfloat16* __restrict__ Thi,
                                     __nv_bfloat16* __restrict__ Tlo, int K, int N)
{
    __shared__ float t[32][33];
    int tx = threadIdx.x, ty = threadIdx.y;          // 32 x 8
    int n0 = blockIdx.x * 32, k0 = blockIdx.y * 32;
    #pragma unroll
    for (int j = 0; j < 4; ++j)
        t[ty + j * 8][tx] = W[(size_t)(k0 + ty + j * 8) * N + n0 + tx];
    __syncthreads();
    #pragma unroll
    for (int j = 0; j < 4; ++j) {
        float v = t[tx][ty + j * 8];
        int n = n0 + ty + j * 8, k = k0 + tx;
        uint32_t u = __float_as_uint(v);
        float hv = __uint_as_float(u & 0xffff0000u);
        Thi[(size_t)n * K + k] = __ushort_as_bfloat16((unsigned short)(u >> 16));
        Tlo[(size_t)n * K + k] = __float2bfloat16(v - hv);
    }
}

// ---------------------------------------------------------------------------
// mma.sync GEMM: C = A @ B^T (B stored [N,K] K-major), split-bf16 x3.
// OCCUPANCY BUILD: BK=32, SA=40 -> 40960 B/stage, 2 stages = 81920 B/CTA
// -> 2 CTAs/SM = 16 warps/SM = 4 warps/scheduler (vs 1-2 before).
// 256 threads, 8 warps in 2x4, warp tile 64x32 (proven R5/R8 layout).
// 2-stage cp.async pipeline (distance 1), ONE barrier per K-chunk.
// BF16OUT: write (hi, lo) bf16 with scale folded; else fp32 (+bias).
// ---------------------------------------------------------------------------
#define SA_G       40                       // GEMM smem row stride (bf16)
#define TILE_G     (128 * SA_G * 2)         // 10240 bytes per tensor tile
#define OFF_AHI    0
#define OFF_ALO    (TILE_G)
#define OFF_BHI    (2 * TILE_G)
#define OFF_BLO    (3 * TILE_G)
#define BUF_G      (4 * TILE_G)             // 40960 per stage
#define GEMM_SMEM  (2 * BUF_G)              // 81920 -> 2 CTAs/SM

template <bool BF16OUT>
__global__ __launch_bounds__(256, 2) void mma_gemm_kernel(
    const __nv_bfloat16* __restrict__ Ahi, const __nv_bfloat16* __restrict__ Alo,
    const __nv_bfloat16* __restrict__ Bhi, const __nv_bfloat16* __restrict__ Blo,
    float* __restrict__ C, __nv_bfloat16* __restrict__ Chi,
    __nv_bfloat16* __restrict__ Clo, float scale,
    int Ndim, int Kdim, const float* __restrict__ bias)
{
    extern __shared__ __align__(128) char smem[];
    const uint32_t sb = smem_u32(smem);
    const int tid = threadIdx.x, wid = tid >> 5, l = tid & 31;
    const int warp_m = wid >> 2, warp_n = wid & 3;
    const int brow = blockIdx.y * 128, bcol = blockIdx.x * 128;

    const int a_row = warp_m * 64 + (l & 7) + ((l >> 3) & 1) * 8;
    const int a_col = ((l >> 4) & 1) * 8;
    const int b_row = warp_n * 32 + (l & 7) + ((l >> 4) & 1) * 8;
    const int b_col = ((l >> 3) & 1) * 8;
    const uint32_t aOff = (uint32_t)(a_row * SA_G + a_col) * 2;
    const uint32_t bOff = (uint32_t)(b_row * SA_G + b_col) * 2;

    float acc[4][4][4];
    #pragma unroll
    for (int im = 0; im < 4; ++im)
        #pragma unroll
        for (int j = 0; j < 4; ++j)
            #pragma unroll
            for (int q = 0; q < 4; ++q) acc[im][j][q] = 0.f;

    const int nch = Kdim >> 5;    // BK = 32

    // Stage one K-chunk (128 rows x 32 bf16 x 4 tensors = 2048 cp.async of 16B)
    auto stage = [&](int ch, int bb) {
        const int k0 = ch << 5;
        const uint32_t base = sb + (uint32_t)bb * BUF_G;
        #pragma unroll
        for (int i = 0; i < 2; ++i) {
            int s = tid + i * 256;           // 0..511 per tensor
            int r = s >> 2, c = s & 3;       // row 0..127, 16B-chunk 0..3
            uint32_t so = (uint32_t)(r * (SA_G * 2) + c * 16);
            size_t ga = (size_t)(brow + r) * Kdim + k0 + c * 8;
            size_t gb = (size_t)(bcol + r) * Kdim + k0 + c * 8;
            cp_async16(base + OFF_AHI + so, Ahi + ga);
            cp_async16(base + OFF_ALO + so, Alo + ga);
            cp_async16(base + OFF_BHI + so, Bhi + gb);
            cp_async16(base + OFF_BLO + so, Blo + gb);
        }
        CP_COMMIT();
    };

    stage(0, 0);

    for (int ch = 0; ch < nch; ++ch) {
        CP_WAIT(0);
        __syncthreads();
        if (ch + 1 < nch) stage(ch + 1, (ch + 1) & 1);

        const uint32_t base = sb + (uint32_t)(ch & 1) * BUF_G;
        #pragma unroll
        for (int ks = 0; ks < 2; ++ks) {
            // B fragments for this k16 step (live: 16 regs)
            uint32_t bhi[4][2], blo[4][2];
            #pragma unroll
            for (int in16 = 0; in16 < 2; ++in16) {
                uint32_t bo = bOff + (uint32_t)(in16 * 16 * SA_G + ks * 16) * 2;
                ldmatrix_x4(bhi[in16 * 2][0], bhi[in16 * 2][1],
                            bhi[in16 * 2 + 1][0], bhi[in16 * 2 + 1][1],
                            base + OFF_BHI + bo);
                ldmatrix_x4(blo[in16 * 2][0], blo[in16 * 2][1],
                            blo[in16 * 2 + 1][0], blo[in16 * 2 + 1][1],
                            base + OFF_BLO + bo);
            }
            // A fragments loaded per-im to keep the live set small
            #pragma unroll
            for (int im = 0; im < 4; ++im) {
                uint32_t ahi[4], alo[4];
                uint32_t ao = aOff + (uint32_t)(im * 16 * SA_G + ks * 16) * 2;
                ldmatrix_x4(ahi[0], ahi[1], ahi[2], ahi[3], base + OFF_AHI + ao);
                ldmatrix_x4(alo[0], alo[1], alo[2], alo[3], base + OFF_ALO + ao);
                #pragma unroll
                for (int j = 0; j < 4; ++j) {
                    mma16816(acc[im][j], ahi, bhi[j]);
                    mma16816(acc[im][j], ahi, blo[j]);
                    mma16816(acc[im][j], alo, bhi[j]);
                }
            }
        }
    }

    #pragma unroll
    for (int im = 0; im < 4; ++im) {
        int row = brow + warp_m * 64 + im * 16 + (l >> 2);
        #pragma unroll
        for (int j = 0; j < 4; ++j) {
            int col = bcol + warp_n * 32 + j * 8 + (l & 3) * 2;
            if (BF16OUT) {
                float v0 = acc[im][j][0] * scale, v1 = acc[im][j][1] * scale;
                float v2 = acc[im][j][2] * scale, v3 = acc[im][j][3] * scale;
                size_t o0 = (size_t)row * Ndim + col;
                size_t o1 = (size_t)(row + 8) * Ndim + col;
                *reinterpret_cast<uint32_t*>(Chi + o0) = pack_hi2(v0, v1);
                *reinterpret_cast<uint32_t*>(Clo + o0) = pack_lo2(v0, v1);
                *reinterpret_cast<uint32_t*>(Chi + o1) = pack_hi2(v2, v3);
                *reinterpret_cast<uint32_t*>(Clo + o1) = pack_lo2(v2, v3);
            } else {
                float2 v0 = {acc[im][j][0], acc[im][j][1]};
                float2 v1 = {acc[im][j][2], acc[im][j][3]};
                if (bias) {
                    float2 bv = *reinterpret_cast<const float2*>(bias + col);
                    v0.x += bv.x; v0.y += bv.y; v1.x += bv.x; v1.y += bv.y;
                }
                *reinterpret_cast<float2*>(C + (size_t)row * Ndim + col) = v0;
                *reinterpret_cast<float2*>(C + (size_t)(row + 8) * Ndim + col) = v1;
            }
        }
    }
}

// ---------------------------------------------------------------------------
// FA2-style attention, mma.sync, split-bf16 x3 on both matmuls (UNCHANGED).
// CTA = (b, h, 128 q rows); 8 warps x 16 rows; kv tile = 64, 2-stage pipeline
// (distance 1), ONE barrier per tile. smem/stage: Khi|Klo|Vhi|Vlo (64x72 bf16).
// ---------------------------------------------------------------------------
#define SA_       72
#define AT_STG    36864
#define AT_SMEM   (2 * AT_STG)              // 73728 (proven envelope)
#define AT_KLO    9216
#define AT_VHI    18432
#define AT_VLO    27648

__global__ __launch_bounds__(256) void attn_mma_kernel(
    const __nv_bfloat16* __restrict__ Qhi, const __nv_bfloat16* __restrict__ Qlo,
    const __nv_bfloat16* __restrict__ Khi, const __nv_bfloat16* __restrict__ Klo,
    const __nv_bfloat16* __restrict__ Vhi, const __nv_bfloat16* __restrict__ Vlo,
    __nv_bfloat16* __restrict__ AOhi, __nv_bfloat16* __restrict__ AOlo)
{
    extern __shared__ __align__(128) char smem[];
    const uint32_t sb = smem_u32(smem);
    const int tid = threadIdx.x, wid = tid >> 5, l = tid & 31;
    const int b = blockIdx.z, h = blockIdx.y;
    const int q0 = blockIdx.x * 128;
    const size_t qrow0 = (size_t)(b * N_ + q0);
    const size_t krow0 = (size_t)(b * M_);
    const int hc = h * 64;

    // ---- Stage Q tile (128 x 64 hi/lo) into stage-0 region, build A frags
    #pragma unroll
    for (int i = 0; i < 4; ++i) {
        int s = tid + i * 256;               // 0..1023
        int r = s >> 3, c = s & 7;
        uint32_t so = (uint32_t)(r * 144 + c * 16);
        size_t g = (qrow0 + r) * INNER + hc + c * 8;
        cp_async16(sb + so, Qhi + g);
        cp_async16(sb + 18432 + so, Qlo + g);
    }
    CP_COMMIT(); CP_WAIT(0);
    __syncthreads();

    uint32_t qh[4][4], ql[4][4];
    {
        int ar = wid * 16 + (l & 7) + ((l >> 3) & 1) * 8;
        int ac = ((l >> 4) & 1) * 8;
        #pragma unroll
        for (int ks = 0; ks < 4; ++ks) {
            uint32_t ad = sb + (uint32_t)(ar * SA_ + ac + ks * 16) * 2;
            ldmatrix_x4(qh[ks][0], qh[ks][1], qh[ks][2], qh[ks][3], ad);
            ldmatrix_x4(ql[ks][0], ql[ks][1], ql[ks][2], ql[ks][3], ad + 18432);
        }
    }
    __syncthreads();

    float o[8][4];
    #pragma unroll
    for (int j = 0; j < 8; ++j)
        #pragma unroll
        for (int q = 0; q < 4; ++q) o[j][q] = 0.f;
    float m0 = -1e30f, m1 = -1e30f, lp0 = 0.f, lp1 = 0.f;

    auto stageKV = [&](int t, int bb) {
        const uint32_t base = sb + (uint32_t)bb * AT_STG;
        const int kv0 = t * 64;
        #pragma unroll
        for (int i = 0; i < 2; ++i) {
            int s = tid + i * 256;           // 0..511
            int r = s >> 3, c = s & 7;
            uint32_t so = (uint32_t)(r * 144 + c * 16);
            size_t g = (krow0 + kv0 + r) * INNER + hc + c * 8;
            cp_async16(base + so,          Khi + g);
            cp_async16(base + AT_KLO + so, Klo + g);
            cp_async16(base + AT_VHI + so, Vhi + g);
            cp_async16(base + AT_VLO + so, Vlo + g);
        }
        CP_COMMIT();
    };

    stageKV(0, 0);

    const int nr  = (l & 7) + ((l >> 4) & 1) * 8;    // K-frag row in tile
    const int kc8 = ((l >> 3) & 1) * 8;              // K-frag col offset
    const int vg  = l >> 3, vi = l & 7;              // V trans-frag coords
    const int NT  = M_ / 64;

    for (int t = 0; t < NT; ++t) {
        CP_WAIT(0);
        __syncthreads();
        if (t + 1 < NT) stageKV(t + 1, (t + 1) & 1);
        const uint32_t kb = sb + (uint32_t)(t & 1) * AT_STG;

        // ---- S = Q K^T (3 split products)
        float s[8][4];
        #pragma unroll
        for (int j = 0; j < 8; ++j)
            #pragma unroll
            for (int q = 0; q < 4; ++q) s[j][q] = 0.f;

        #pragma unroll
        for (int ks = 0; ks < 4; ++ks) {
            #pragma unroll
            for (int jn = 0; jn < 4; ++jn) {
                uint32_t ad = kb + (uint32_t)((jn * 16 + nr) * SA_ + ks * 16 + kc8) * 2;
                uint32_t h0, h1, h2, h3, l0, l1, l2, l3;
                ldmatrix_x4(h0, h1, h2, h3, ad);
                ldmatrix_x4(l0, l1, l2, l3, ad + AT_KLO);
                uint32_t bh0[2] = {h0, h1}, bh1[2] = {h2, h3};
                uint32_t bl0[2] = {l0, l1}, bl1[2] = {l2, l3};
                mma16816(s[2 * jn],     qh[ks], bh0);
                mma16816(s[2 * jn],     qh[ks], bl0);
                mma16816(s[2 * jn],     ql[ks], bh0);
                mma16816(s[2 * jn + 1], qh[ks], bh1);
                mma16816(s[2 * jn + 1], qh[ks], bl1);
                mma16816(s[2 * jn + 1], ql[ks], bh1);
            }
        }

        // ---- online softmax (rows r = l/4 and r+8)
        float mx0 = -1e30f, mx1 = -1e30f;
        #pragma unroll
        for (int j = 0; j < 8; ++j) {
            mx0 = fmaxf(mx0, fmaxf(s[j][0], s[j][1]));
            mx1 = fmaxf(mx1, fmaxf(s[j][2], s[j][3]));
        }
        mx0 = fmaxf(mx0, __shfl_xor_sync(0xffffffffu, mx0, 1));
        mx0 = fmaxf(mx0, __shfl_xor_sync(0xffffffffu, mx0, 2));
        mx1 = fmaxf(mx1, __shfl_xor_sync(0xffffffffu, mx1, 1));
        mx1 = fmaxf(mx1, __shfl_xor_sync(0xffffffffu, mx1, 2));

        float nm0 = fmaxf(m0, mx0), nm1 = fmaxf(m1, mx1);
        float al0 = __expf(m0 - nm0), al1 = __expf(m1 - nm1);
        m0 = nm0; m1 = nm1;

        float add0 = 0.f, add1 = 0.f;
        #pragma unroll
        for (int j = 0; j < 8; ++j) {
            s[j][0] = __expf(s[j][0] - nm0);
            s[j][1] = __expf(s[j][1] - nm0);
            s[j][2] = __expf(s[j][2] - nm1);
            s[j][3] = __expf(s[j][3] - nm1);
            add0 += s[j][0] + s[j][1];
            add1 += s[j][2] + s[j][3];
        }
        lp0 = lp0 * al0 + add0;
        lp1 = lp1 * al1 + add1;
        #pragma unroll
        for (int j = 0; j < 8; ++j) {
            o[j][0] *= al0; o[j][1] *= al0;
            o[j][2] *= al1; o[j][3] *= al1;
        }

        // ---- AV (3 split products), P frags built from s in-registers
        #pragma unroll
        for (int t2 = 0; t2 < 4; ++t2) {
            uint32_t pah[4], pal[4];
            pah[0] = pack_hi2(s[2 * t2][0],     s[2 * t2][1]);
            pah[1] = pack_hi2(s[2 * t2][2],     s[2 * t2][3]);
            pah[2] = pack_hi2(s[2 * t2 + 1][0], s[2 * t2 + 1][1]);
            pah[3] = pack_hi2(s[2 * t2 + 1][2], s[2 * t2 + 1][3]);
            pal[0] = pack_lo2(s[2 * t2][0],     s[2 * t2][1]);
            pal[1] = pack_lo2(s[2 * t2][2],     s[2 * t2][3]);
            pal[2] = pack_lo2(s[2 * t2 + 1][0], s[2 * t2 + 1][1]);
            pal[3] = pack_lo2(s[2 * t2 + 1][2], s[2 * t2 + 1][3]);

            #pragma unroll
            for (int jn = 0; jn < 4; ++jn) {
                uint32_t ad = kb + AT_VHI +
                    (uint32_t)((t2 * 16 + (vg & 1) * 8 + vi) * SA_ +
                               jn * 16 + (vg >> 1) * 8) * 2;
                uint32_t h0, h1, h2, h3, l0, l1, l2, l3;
                ldmatrix_x4_t(h0, h1, h2, h3, ad);
                ldmatrix_x4_t(l0, l1, l2, l3, ad + (AT_VLO - AT_VHI));
                uint32_t bh0[2] = {h0, h1}, bh1[2] = {h2, h3};
                uint32_t bl0[2] = {l0, l1}, bl1[2] = {l2, l3};
                mma16816(o[2 * jn],     pah, bh0);
                mma16816(o[2 * jn],     pah, bl0);
                mma16816(o[2 * jn],     pal, bh0);
                mma16816(o[2 * jn + 1], pah, bh1);
                mma16816(o[2 * jn + 1], pah, bl1);
                mma16816(o[2 * jn + 1], pal, bh1);
            }
        }
    }

    // ---- normalize + write hi/lo bf16
    lp0 += __shfl_xor_sync(0xffffffffu, lp0, 1);
    lp0 += __shfl_xor_sync(0xffffffffu, lp0, 2);
    lp1 += __shfl_xor_sync(0xffffffffu, lp1, 1);
    lp1 += __shfl_xor_sync(0xffffffffu, lp1, 2);
    float inv0 = 1.f / lp0, inv1 = 1.f / lp1;

    size_t r0g = (qrow0 + wid * 16 + (l >> 2)) * INNER + hc;
    size_t r1g = r0g + (size_t)8 * INNER;
    #pragma unroll
    for (int j = 0; j < 8; ++j) {
        int c = j * 8 + (l & 3) * 2;
        float v0 = o[j][0] * inv0, v1 = o[j][1] * inv0;
        float v2 = o[j][2] * inv1, v3 = o[j][3] * inv1;
        *reinterpret_cast<uint32_t*>(AOhi + r0g + c) = pack_hi2(v0, v1);
        *reinterpret_cast<uint32_t*>(AOlo + r0g + c) = pack_lo2(v0, v1);
        *reinterpret_cast<uint32_t*>(AOhi + r1g + c) = pack_hi2(v2, v3);
        *reinterpret_cast<uint32_t*>(AOlo + r1g + c) = pack_lo2(v2, v3);
    }
}

// ---------------------------------------------------------------------------
// Launch
// ---------------------------------------------------------------------------
extern "C" void kernel_launch(void* const* d_in, const int* in_sizes, int n_in,
                              void* d_out, int out_size)
{
    const float* x   = (const float*)d_in[0];
    const float* ctx = (const float*)d_in[1];
    const float* Wq  = (const float*)d_in[2];
    const float* Wk  = (const float*)d_in[3];
    const float* Wv  = (const float*)d_in[4];
    const float* Wo  = (const float*)d_in[5];
    const float* bo  = (const float*)d_in[6];
    float* out = (float*)d_out;

    cudaFuncSetAttribute(mma_gemm_kernel<true>,
                         cudaFuncAttributeMaxDynamicSharedMemorySize, GEMM_SMEM);
    cudaFuncSetAttribute(mma_gemm_kernel<false>,
                         cudaFuncAttributeMaxDynamicSharedMemorySize, GEMM_SMEM);
    cudaFuncSetAttribute(attn_mma_kernel,
                         cudaFuncAttributeMaxDynamicSharedMemorySize, AT_SMEM);

    __nv_bfloat16 *qhi, *qlo, *khi, *klo, *vhi, *vlo;
    __nv_bfloat16 *xhi, *xlo, *chi, *clo, *aohi, *aolo;
    __nv_bfloat16 *wqh, *wql, *wkh, *wkl, *wvh, *wvl, *woh, *wol;
    cudaGetSymbolAddress((void**)&qhi, g_Qhi);  cudaGetSymbolAddress((void**)&qlo, g_Qlo);
    cudaGetSymbolAddress((void**)&khi, g_Khi);  cudaGetSymbolAddress((void**)&klo, g_Klo);
    cudaGetSymbolAddress((void**)&vhi, g_Vhi);  cudaGetSymbolAddress((void**)&vlo, g_Vlo);
    cudaGetSymbolAddress((void**)&xhi, g_xhi);  cudaGetSymbolAddress((void**)&xlo, g_xlo);
    cudaGetSymbolAddress((void**)&chi, g_chi);  cudaGetSymbolAddress((void**)&clo, g_clo);
    cudaGetSymbolAddress((void**)&aohi, g_AOhi); cudaGetSymbolAddress((void**)&aolo, g_AOlo);
    cudaGetSymbolAddress((void**)&wqh, g_WqThi); cudaGetSymbolAddress((void**)&wql, g_WqTlo);
    cudaGetSymbolAddress((void**)&wkh, g_WkThi); cudaGetSymbolAddress((void**)&wkl, g_WkTlo);
    cudaGetSymbolAddress((void**)&wvh, g_WvThi); cudaGetSymbolAddress((void**)&wvl, g_WvTlo);
    cudaGetSymbolAddress((void**)&woh, g_WoThi); cudaGetSymbolAddress((void**)&wol, g_WoTlo);

    // 1. Split-convert inputs
    {
        int n4 = (BNQ * QD_) / 4;
        cvt_hilo_kernel<<<n4 / 256, 256>>>(x, xhi, xlo, n4);
        n4 = (BMC * CD_) / 4;
        cvt_hilo_kernel<<<n4 / 256, 256>>>(ctx, chi, clo, n4);
    }
    transpose_cvt_kernel<<<dim3(INNER / 32, QD_ / 32), dim3(32, 8)>>>(Wq, wqh, wql, QD_, INNER);
    transpose_cvt_kernel<<<dim3(INNER / 32, CD_ / 32), dim3(32, 8)>>>(Wk, wkh, wkl, CD_, INNER);
    transpose_cvt_kernel<<<dim3(INNER / 32, CD_ / 32), dim3(32, 8)>>>(Wv, wvh, wvl, CD_, INNER);
    transpose_cvt_kernel<<<dim3(QD_ / 32, INNER / 32), dim3(32, 8)>>>(Wo, woh, wol, INNER, QD_);

    // 2. Projections -> hi/lo bf16 (Q with softmax scale folded in)
    mma_gemm_kernel<true><<<dim3(INNER / 128, BNQ / 128), 256, GEMM_SMEM>>>(
        xhi, xlo, wqh, wql, nullptr, qhi, qlo, 0.125f, INNER, QD_, nullptr);
    mma_gemm_kernel<true><<<dim3(INNER / 128, BMC / 128), 256, GEMM_SMEM>>>(
        chi, clo, wkh, wkl, nullptr, khi, klo, 1.0f, INNER, CD_, nullptr);
    mma_gemm_kernel<true><<<dim3(INNER / 128, BMC / 128), 256, GEMM_SMEM>>>(
        chi, clo, wvh, wvl, nullptr, vhi, vlo, 1.0f, INNER, CD_, nullptr);

    // 3. Attention (tensor-core FA2)
    attn_mma_kernel<<<dim3(N_ / 128, H_, B_), 256, AT_SMEM>>>(
        qhi, qlo, khi, klo, vhi, vlo, aohi, aolo);

    // 4. Output projection + bias -> d_out (fp32)
    mma_gemm_kernel<false><<<dim3(QD_ / 128, BNQ / 128), 256, GEMM_SMEM>>>(
        aohi, aolo, woh, wol, out, nullptr, nullptr, 1.0f, QD_, INNER, bo);
}

// round 14
// speedup vs baseline: 1.4168x; 1.3721x over previous
#include <cuda_runtime.h>
#include <cuda_fp16.h>
#include <cstdint>
#include <cstddef>

// Problem constants
#define B_    4
#define N_    4096
#define M_    1024
#define QD_   1024
#define CD_   768
#define H_    16
#define D_    64
#define INNER 1024
#define BNQ   (B_ * N_)   // 16384 query rows
#define BMC   (B_ * M_)   // 4096 context rows

// ---------------------------------------------------------------------------
// Static device scratch (fp16 era: A-side operands split hi/lo, B-side single)
// ---------------------------------------------------------------------------
__device__ __half g_Qhi[BNQ * INNER], g_Qlo[BNQ * INNER];
__device__ __half g_K  [BMC * INNER];          // single fp16 (B-side of QK^T)
__device__ __half g_V  [BMC * INNER];          // single fp16 (B-side of AV)
__device__ __half g_xhi[BNQ * QD_],  g_xlo[BNQ * QD_];
__device__ __half g_chi[BMC * CD_],  g_clo[BMC * CD_];
__device__ __half g_WqT[INNER * QD_];          // weights: single fp16, [N,K]
__device__ __half g_WkT[INNER * CD_];
__device__ __half g_WvT[INNER * CD_];
__device__ __half g_WoT[QD_ * INNER];
__device__ __half g_AOhi[BNQ * INNER], g_AOlo[BNQ * INNER];

// ---------------------------------------------------------------------------
// PTX helpers
// ---------------------------------------------------------------------------
__device__ __forceinline__ uint32_t smem_u32(const void* p) {
    uint32_t a;
    asm("{ .reg .u64 t; cvta.to.shared.u64 t, %1; cvt.u32.u64 %0, t; }"
        : "=r"(a) : "l"(p));
    return a;
}

__device__ __forceinline__ void cp_async16(uint32_t dst, const void* src) {
    asm volatile("cp.async.cg.shared.global [%0], [%1], 16;"
                 :: "r"(dst), "l"(src) : "memory");
}
#define CP_COMMIT() asm volatile("cp.async.commit_group;" ::: "memory")
#define CP_WAIT(n)  asm volatile("cp.async.wait_group %0;" :: "n"(n) : "memory")

__device__ __forceinline__ void ldmatrix_x4(uint32_t& r0, uint32_t& r1,
                                            uint32_t& r2, uint32_t& r3, uint32_t a) {
    asm volatile("ldmatrix.sync.aligned.m8n8.x4.shared.b16 {%0,%1,%2,%3}, [%4];"
                 : "=r"(r0), "=r"(r1), "=r"(r2), "=r"(r3) : "r"(a));
}

__device__ __forceinline__ void ldmatrix_x4_t(uint32_t& r0, uint32_t& r1,
                                              uint32_t& r2, uint32_t& r3, uint32_t a) {
    asm volatile("ldmatrix.sync.aligned.m8n8.x4.trans.shared.b16 {%0,%1,%2,%3}, [%4];"
                 : "=r"(r0), "=r"(r1), "=r"(r2), "=r"(r3) : "r"(a));
}

// fp16 x fp16 -> fp32 accumulate
__device__ __forceinline__ void mma16816(float* d, const uint32_t* a,
                                         const uint32_t* b) {
    asm volatile(
        "mma.sync.aligned.m16n8k16.row.col.f32.f16.f16.f32 "
        "{%0,%1,%2,%3}, {%4,%5,%6,%7}, {%8,%9}, {%0,%1,%2,%3};"
        : "+f"(d[0]), "+f"(d[1]), "+f"(d[2]), "+f"(d[3])
        : "r"(a[0]), "r"(a[1]), "r"(a[2]), "r"(a[3]), "r"(b[0]), "r"(b[1]));
}

// Pack two floats as fp16x2 (element0 = low half = v0)
__device__ __forceinline__ uint32_t packh2(float v0, float v1) {
    __half2 h = __floats2half2_rn(v0, v1);
    return *reinterpret_cast<uint32_t*>(&h);
}
// rn hi + residual lo split
__device__ __forceinline__ void splith2(float v0, float v1,
                                        uint32_t& hi, uint32_t& lo) {
    __half2 h = __floats2half2_rn(v0, v1);
    float2 hf = __half22float2(h);
    __half2 l = __floats2half2_rn(v0 - hf.x, v1 - hf.y);
    hi = *reinterpret_cast<uint32_t*>(&h);
    lo = *reinterpret_cast<uint32_t*>(&l);
}

// ---------------------------------------------------------------------------
// Conversion kernels
// ---------------------------------------------------------------------------
__global__ void cvt_split_kernel(const float* __restrict__ in,
                                 __half* __restrict__ hi,
                                 __half* __restrict__ lo, int n4)
{
    int i = blockIdx.x * blockDim.x + threadIdx.x;
    if (i >= n4) return;
    float4 v = reinterpret_cast<const float4*>(in)[i];
    uint32_t h0, l0, h1, l1;
    splith2(v.x, v.y, h0, l0);
    splith2(v.z, v.w, h1, l1);
    reinterpret_cast<uint32_t*>(hi)[i * 2 + 0] = h0;
    reinterpret_cast<uint32_t*>(hi)[i * 2 + 1] = h1;
    reinterpret_cast<uint32_t*>(lo)[i * 2 + 0] = l0;
    reinterpret_cast<uint32_t*>(lo)[i * 2 + 1] = l1;
}

// W [K,N] row-major  ->  T [N,K] single fp16
__global__ void transpose_cvt_kernel(const float* __restrict__ W,
                                     __half* __restrict__ T, int K, int N)
{
    __shared__ float t[32][33];
    int tx = threadIdx.x, ty = threadIdx.y;          // 32 x 8
    int n0 = blockIdx.x * 32, k0 = blockIdx.y * 32;
    #pragma unroll
    for (int j = 0; j < 4; ++j)
        t[ty + j * 8][tx] = W[(size_t)(k0 + ty + j * 8) * N + n0 + tx];
    __syncthreads();
    #pragma unroll
    for (int j = 0; j < 4; ++j) {
        float v = t[tx][ty + j * 8];
        int n = n0 + ty + j * 8, k = k0 + tx;
        T[(size_t)n * K + k] = __float2half_rn(v);
    }
}

// ---------------------------------------------------------------------------
// fp16 GEMM: C = A @ B^T, A split (hi+lo), B single. 2 MMAs per k16 tile.
// BK=32, SA_G=40 halfs -> 3 tensors x 10240 B = 30720/stage, 2 stages
// = 61440 B/CTA -> 2 CTAs/SM. 256 threads, 8 warps 2x4, warp tile 64x32.
// OUTMODE: 0 = split fp16 (hi/lo, scale folded), 1 = single fp16, 2 = fp32+bias
// ---------------------------------------------------------------------------
#define SA_G       40
#define TILE_G     (128 * SA_G * 2)          // 10240 B
#define OFF_AHI    0
#define OFF_ALO    (TILE_G)
#define OFF_B      (2 * TILE_G)
#define BUF_G      (3 * TILE_G)              // 30720 per stage
#define GEMM_SMEM  (2 * BUF_G)               // 61440

template <int OUTMODE>
__global__ __launch_bounds__(256, 2) void mma_gemm_kernel(
    const __half* __restrict__ Ahi, const __half* __restrict__ Alo,
    const __half* __restrict__ Bs,
    float* __restrict__ C, __half* __restrict__ Chi, __half* __restrict__ Clo,
    float scale, int Ndim, int Kdim, const float* __restrict__ bias)
{
    extern __shared__ __align__(128) char smem[];
    const uint32_t sb = smem_u32(smem);
    const int tid = threadIdx.x, wid = tid >> 5, l = tid & 31;
    const int warp_m = wid >> 2, warp_n = wid & 3;
    const int brow = blockIdx.y * 128, bcol = blockIdx.x * 128;

    const int a_row = warp_m * 64 + (l & 7) + ((l >> 3) & 1) * 8;
    const int a_col = ((l >> 4) & 1) * 8;
    const int b_row = warp_n * 32 + (l & 7) + ((l >> 4) & 1) * 8;
    const int b_col = ((l >> 3) & 1) * 8;
    const uint32_t aOff = (uint32_t)(a_row * SA_G + a_col) * 2;
    const uint32_t bOff = (uint32_t)(b_row * SA_G + b_col) * 2;

    float acc[4][4][4];
    #pragma unroll
    for (int im = 0; im < 4; ++im)
        #pragma unroll
        for (int j = 0; j < 4; ++j)
            #pragma unroll
            for (int q = 0; q < 4; ++q) acc[im][j][q] = 0.f;

    const int nch = Kdim >> 5;    // BK = 32

    auto stage = [&](int ch, int bb) {
        const int k0 = ch << 5;
        const uint32_t base = sb + (uint32_t)bb * BUF_G;
        #pragma unroll
        for (int i = 0; i < 2; ++i) {
            int s = tid + i * 256;           // 0..511 per tensor
            int r = s >> 2, c = s & 3;       // row, 16B chunk
            uint32_t so = (uint32_t)(r * (SA_G * 2) + c * 16);
            size_t ga = (size_t)(brow + r) * Kdim + k0 + c * 8;
            size_t gb = (size_t)(bcol + r) * Kdim + k0 + c * 8;
            cp_async16(base + OFF_AHI + so, Ahi + ga);
            cp_async16(base + OFF_ALO + so, Alo + ga);
            cp_async16(base + OFF_B   + so, Bs  + gb);
        }
        CP_COMMIT();
    };

    stage(0, 0);

    for (int ch = 0; ch < nch; ++ch) {
        CP_WAIT(0);
        __syncthreads();
        if (ch + 1 < nch) stage(ch + 1, (ch + 1) & 1);

        const uint32_t base = sb + (uint32_t)(ch & 1) * BUF_G;
        #pragma unroll
        for (int ks = 0; ks < 2; ++ks) {
            uint32_t bf[4][2];
            #pragma unroll
            for (int in16 = 0; in16 < 2; ++in16) {
                uint32_t bo = bOff + (uint32_t)(in16 * 16 * SA_G + ks * 16) * 2;
                ldmatrix_x4(bf[in16 * 2][0], bf[in16 * 2][1],
                            bf[in16 * 2 + 1][0], bf[in16 * 2 + 1][1],
                            base + OFF_B + bo);
            }
            #pragma unroll
            for (int im = 0; im < 4; ++im) {
                uint32_t ahi[4], alo[4];
                uint32_t ao = aOff + (uint32_t)(im * 16 * SA_G + ks * 16) * 2;
                ldmatrix_x4(ahi[0], ahi[1], ahi[2], ahi[3], base + OFF_AHI + ao);
                ldmatrix_x4(alo[0], alo[1], alo[2], alo[3], base + OFF_ALO + ao);
                #pragma unroll
                for (int j = 0; j < 4; ++j) {
                    mma16816(acc[im][j], ahi, bf[j]);
                    mma16816(acc[im][j], alo, bf[j]);
                }
            }
        }
    }

    #pragma unroll
    for (int im = 0; im < 4; ++im) {
        int row = brow + warp_m * 64 + im * 16 + (l >> 2);
        #pragma unroll
        for (int j = 0; j < 4; ++j) {
            int col = bcol + warp_n * 32 + j * 8 + (l & 3) * 2;
            float v0 = acc[im][j][0] * scale, v1 = acc[im][j][1] * scale;
            float v2 = acc[im][j][2] * scale, v3 = acc[im][j][3] * scale;
            size_t o0 = (size_t)row * Ndim + col;
            size_t o1 = (size_t)(row + 8) * Ndim + col;
            if (OUTMODE == 0) {
                uint32_t h, lo;
                splith2(v0, v1, h, lo);
                *reinterpret_cast<uint32_t*>(Chi + o0) = h;
                *reinterpret_cast<uint32_t*>(Clo + o0) = lo;
                splith2(v2, v3, h, lo);
                *reinterpret_cast<uint32_t*>(Chi + o1) = h;
                *reinterpret_cast<uint32_t*>(Clo + o1) = lo;
            } else if (OUTMODE == 1) {
                *reinterpret_cast<uint32_t*>(Chi + o0) = packh2(v0, v1);
                *reinterpret_cast<uint32_t*>(Chi + o1) = packh2(v2, v3);
            } else {
                float2 w0 = {v0, v1}, w1 = {v2, v3};
                if (bias) {
                    float2 bv = *reinterpret_cast<const float2*>(bias + col);
                    w0.x += bv.x; w0.y += bv.y; w1.x += bv.x; w1.y += bv.y;
                }
                *reinterpret_cast<float2*>(C + o0) = w0;
                *reinterpret_cast<float2*>(C + o1) = w1;
            }
        }
    }
}

// ---------------------------------------------------------------------------
// FA2 attention (fp16): Q split (A-side), K/V single (B-side). 2-MMA products.
// CTA = (b, h, 128 q rows); 8 warps x 16 rows; kv tile = 64, 2-stage pipeline.
// smem/stage: K | V, each 64 x 72 halfs (9216 B) -> 18432/stage, 36864 total.
// ---------------------------------------------------------------------------
#define SA_       72
#define AT_STG    18432
#define AT_SMEM   (2 * AT_STG)
#define AT_V      9216

__global__ __launch_bounds__(256) void attn_mma_kernel(
    const __half* __restrict__ Qhi, const __half* __restrict__ Qlo,
    const __half* __restrict__ Ks,  const __half* __restrict__ Vs,
    __half* __restrict__ AOhi, __half* __restrict__ AOlo)
{
    extern __shared__ __align__(128) char smem[];
    const uint32_t sb = smem_u32(smem);
    const int tid = threadIdx.x, wid = tid >> 5, l = tid & 31;
    const int b = blockIdx.z, h = blockIdx.y;
    const int q0 = blockIdx.x * 128;
    const size_t qrow0 = (size_t)(b * N_ + q0);
    const size_t krow0 = (size_t)(b * M_);
    const int hc = h * 64;

    // ---- Stage Q tile (128 x 64 hi/lo) across the two stage regions
    #pragma unroll
    for (int i = 0; i < 4; ++i) {
        int s = tid + i * 256;               // 0..1023
        int r = s >> 3, c = s & 7;
        uint32_t so = (uint32_t)(r * 144 + c * 16);
        size_t g = (qrow0 + r) * INNER + hc + c * 8;
        cp_async16(sb + so,         Qhi + g);
        cp_async16(sb + 18432 + so, Qlo + g);
    }
    CP_COMMIT(); CP_WAIT(0);
    __syncthreads();

    uint32_t qh[4][4], ql[4][4];
    {
        int ar = wid * 16 + (l & 7) + ((l >> 3) & 1) * 8;
        int ac = ((l >> 4) & 1) * 8;
        #pragma unroll
        for (int ks = 0; ks < 4; ++ks) {
            uint32_t ad = sb + (uint32_t)(ar * SA_ + ac + ks * 16) * 2;
            ldmatrix_x4(qh[ks][0], qh[ks][1], qh[ks][2], qh[ks][3], ad);
            ldmatrix_x4(ql[ks][0], ql[ks][1], ql[ks][2], ql[ks][3], ad + 18432);
        }
    }
    __syncthreads();

    float o[8][4];
    #pragma unroll
    for (int j = 0; j < 8; ++j)
        #pragma unroll
        for (int q = 0; q < 4; ++q) o[j][q] = 0.f;
    float m0 = -1e30f, m1 = -1e30f, lp0 = 0.f, lp1 = 0.f;

    auto stageKV = [&](int t, int bb) {
        const uint32_t base = sb + (uint32_t)bb * AT_STG;
        const int kv0 = t * 64;
        #pragma unroll
        for (int i = 0; i < 2; ++i) {
            int s = tid + i * 256;           // 0..511
            int r = s >> 3, c = s & 7;
            uint32_t so = (uint32_t)(r * 144 + c * 16);
            size_t g = (krow0 + kv0 + r) * INNER + hc + c * 8;
            cp_async16(base + so,        Ks + g);
            cp_async16(base + AT_V + so, Vs + g);
        }
        CP_COMMIT();
    };

    stageKV(0, 0);

    const int nr  = (l & 7) + ((l >> 4) & 1) * 8;
    const int kc8 = ((l >> 3) & 1) * 8;
    const int vg  = l >> 3, vi = l & 7;
    const int NT  = M_ / 64;

    for (int t = 0; t < NT; ++t) {
        CP_WAIT(0);
        __syncthreads();
        if (t + 1 < NT) stageKV(t + 1, (t + 1) & 1);
        const uint32_t kb = sb + (uint32_t)(t & 1) * AT_STG;

        // ---- S = (Qhi + Qlo) K^T  (2 products)
        float s[8][4];
        #pragma unroll
        for (int j = 0; j < 8; ++j)
            #pragma unroll
            for (int q = 0; q < 4; ++q) s[j][q] = 0.f;

        #pragma unroll
        for (int ks = 0; ks < 4; ++ks) {
            #pragma unroll
            for (int jn = 0; jn < 4; ++jn) {
                uint32_t ad = kb + (uint32_t)((jn * 16 + nr) * SA_ + ks * 16 + kc8) * 2;
                uint32_t k0, k1, k2, k3;
                ldmatrix_x4(k0, k1, k2, k3, ad);
                uint32_t b0[2] = {k0, k1}, b1[2] = {k2, k3};
                mma16816(s[2 * jn],     qh[ks], b0);
                mma16816(s[2 * jn],     ql[ks], b0);
                mma16816(s[2 * jn + 1], qh[ks], b1);
                mma16816(s[2 * jn + 1], ql[ks], b1);
            }
        }

        // ---- online softmax
        float mx0 = -1e30f, mx1 = -1e30f;
        #pragma unroll
        for (int j = 0; j < 8; ++j) {
            mx0 = fmaxf(mx0, fmaxf(s[j][0], s[j][1]));
            mx1 = fmaxf(mx1, fmaxf(s[j][2], s[j][3]));
        }
        mx0 = fmaxf(mx0, __shfl_xor_sync(0xffffffffu, mx0, 1));
        mx0 = fmaxf(mx0, __shfl_xor_sync(0xffffffffu, mx0, 2));
        mx1 = fmaxf(mx1, __shfl_xor_sync(0xffffffffu, mx1, 1));
        mx1 = fmaxf(mx1, __shfl_xor_sync(0xffffffffu, mx1, 2));

        float nm0 = fmaxf(m0, mx0), nm1 = fmaxf(m1, mx1);
        float al0 = __expf(m0 - nm0), al1 = __expf(m1 - nm1);
        m0 = nm0; m1 = nm1;

        float add0 = 0.f, add1 = 0.f;
        #pragma unroll
        for (int j = 0; j < 8; ++j) {
            s[j][0] = __expf(s[j][0] - nm0);
            s[j][1] = __expf(s[j][1] - nm0);
            s[j][2] = __expf(s[j][2] - nm1);
            s[j][3] = __expf(s[j][3] - nm1);
            add0 += s[j][0] + s[j][1];
            add1 += s[j][2] + s[j][3];
        }
        lp0 = lp0 * al0 + add0;
        lp1 = lp1 * al1 + add1;
        #pragma unroll
        for (int j = 0; j < 8; ++j) {
            o[j][0] *= al0; o[j][1] *= al0;
            o[j][2] *= al1; o[j][3] *= al1;
        }

        // ---- AV: (Phi + Plo) V  (2 products), P split in-registers
        #pragma unroll
        for (int t2 = 0; t2 < 4; ++t2) {
            uint32_t pah[4], pal[4];
            splith2(s[2 * t2][0],     s[2 * t2][1],     pah[0], pal[0]);
            splith2(s[2 * t2][2],     s[2 * t2][3],     pah[1], pal[1]);
            splith2(s[2 * t2 + 1][0], s[2 * t2 + 1][1], pah[2], pal[2]);
            splith2(s[2 * t2 + 1][2], s[2 * t2 + 1][3], pah[3], pal[3]);

            #pragma unroll
            for (int jn = 0; jn < 4; ++jn) {
                uint32_t ad = kb + AT_V +
                    (uint32_t)((t2 * 16 + (vg & 1) * 8 + vi) * SA_ +
                               jn * 16 + (vg >> 1) * 8) * 2;
                uint32_t v0, v1, v2, v3;
                ldmatrix_x4_t(v0, v1, v2, v3, ad);
                uint32_t b0[2] = {v0, v1}, b1[2] = {v2, v3};
                mma16816(o[2 * jn],     pah, b0);
                mma16816(o[2 * jn],     pal, b0);
                mma16816(o[2 * jn + 1], pah, b1);
                mma16816(o[2 * jn + 1], pal, b1);
            }
        }
    }

    // ---- normalize + write hi/lo fp16
    lp0 += __shfl_xor_sync(0xffffffffu, lp0, 1);
    lp0 += __shfl_xor_sync(0xffffffffu, lp0, 2);
    lp1 += __shfl_xor_sync(0xffffffffu, lp1, 1);
    lp1 += __shfl_xor_sync(0xffffffffu, lp1, 2);
    float inv0 = 1.f / lp0, inv1 = 1.f / lp1;

    size_t r0g = (qrow0 + wid * 16 + (l >> 2)) * INNER + hc;
    size_t r1g = r0g + (size_t)8 * INNER;
    #pragma unroll
    for (int j = 0; j < 8; ++j) {
        int c = j * 8 + (l & 3) * 2;
        uint32_t h, lo;
        splith2(o[j][0] * inv0, o[j][1] * inv0, h, lo);
        *reinterpret_cast<uint32_t*>(AOhi + r0g + c) = h;
        *reinterpret_cast<uint32_t*>(AOlo + r0g + c) = lo;
        splith2(o[j][2] * inv1, o[j][3] * inv1, h, lo);
        *reinterpret_cast<uint32_t*>(AOhi + r1g + c) = h;
        *reinterpret_cast<uint32_t*>(AOlo + r1g + c) = lo;
    }
}

// ---------------------------------------------------------------------------
// Launch
// ---------------------------------------------------------------------------
extern "C" void kernel_launch(void* const* d_in, const int* in_sizes, int n_in,
                              void* d_out, int out_size)
{
    const float* x   = (const float*)d_in[0];
    const float* ctx = (const float*)d_in[1];
    const float* Wq  = (const float*)d_in[2];
    const float* Wk  = (const float*)d_in[3];
    const float* Wv  = (const float*)d_in[4];
    const float* Wo  = (const float*)d_in[5];
    const float* bo  = (const float*)d_in[6];
    float* out = (float*)d_out;

    cudaFuncSetAttribute(mma_gemm_kernel<0>,
                         cudaFuncAttributeMaxDynamicSharedMemorySize, GEMM_SMEM);
    cudaFuncSetAttribute(mma_gemm_kernel<1>,
                         cudaFuncAttributeMaxDynamicSharedMemorySize, GEMM_SMEM);
    cudaFuncSetAttribute(mma_gemm_kernel<2>,
                         cudaFuncAttributeMaxDynamicSharedMemorySize, GEMM_SMEM);
    cudaFuncSetAttribute(attn_mma_kernel,
                         cudaFuncAttributeMaxDynamicSharedMemorySize, AT_SMEM);

    __half *qhi, *qlo, *ks, *vs, *xhi, *xlo, *chi, *clo, *aohi, *aolo;
    __half *wqT, *wkT, *wvT, *woT;
    cudaGetSymbolAddress((void**)&qhi, g_Qhi);  cudaGetSymbolAddress((void**)&qlo, g_Qlo);
    cudaGetSymbolAddress((void**)&ks,  g_K);    cudaGetSymbolAddress((void**)&vs,  g_V);
    cudaGetSymbolAddress((void**)&xhi, g_xhi);  cudaGetSymbolAddress((void**)&xlo, g_xlo);
    cudaGetSymbolAddress((void**)&chi, g_chi);  cudaGetSymbolAddress((void**)&clo, g_clo);
    cudaGetSymbolAddress((void**)&aohi, g_AOhi); cudaGetSymbolAddress((void**)&aolo, g_AOlo);
    cudaGetSymbolAddress((void**)&wqT, g_WqT);  cudaGetSymbolAddress((void**)&wkT, g_WkT);
    cudaGetSymbolAddress((void**)&wvT, g_WvT);  cudaGetSymbolAddress((void**)&woT, g_WoT);

    // 1. Split-convert A-side inputs; single-convert weights (transposed)
    {
        int n4 = (BNQ * QD_) / 4;
        cvt_split_kernel<<<n4 / 256, 256>>>(x, xhi, xlo, n4);
        n4 = (BMC * CD_) / 4;
        cvt_split_kernel<<<n4 / 256, 256>>>(ctx, chi, clo, n4);
    }
    transpose_cvt_kernel<<<dim3(INNER / 32, QD_ / 32), dim3(32, 8)>>>(Wq, wqT, QD_, INNER);
    transpose_cvt_kernel<<<dim3(INNER / 32, CD_ / 32), dim3(32, 8)>>>(Wk, wkT, CD_, INNER);
    transpose_cvt_kernel<<<dim3(INNER / 32, CD_ / 32), dim3(32, 8)>>>(Wv, wvT, CD_, INNER);
    transpose_cvt_kernel<<<dim3(QD_ / 32, INNER / 32), dim3(32, 8)>>>(Wo, woT, INNER, QD_);

    // 2. Projections: Q -> split fp16 (softmax scale folded), K/V -> single fp16
    mma_gemm_kernel<0><<<dim3(INNER / 128, BNQ / 128), 256, GEMM_SMEM>>>(
        xhi, xlo, wqT, nullptr, qhi, qlo, 0.125f, INNER, QD_, nullptr);
    mma_gemm_kernel<1><<<dim3(INNER / 128, BMC / 128), 256, GEMM_SMEM>>>(
        chi, clo, wkT, nullptr, ks, nullptr, 1.0f, INNER, CD_, nullptr);
    mma_gemm_kernel<1><<<dim3(INNER / 128, BMC / 128), 256, GEMM_SMEM>>>(
        chi, clo, wvT, nullptr, vs, nullptr, 1.0f, INNER, CD_, nullptr);

    // 3. Attention (fp16 2-product FA2)
    attn_mma_kernel<<<dim3(N_ / 128, H_, B_), 256, AT_SMEM>>>(
        qhi, qlo, ks, vs, aohi, aolo);

    // 4. Output projection + bias -> d_out (fp32)
    mma_gemm_kernel<2><<<dim3(QD_ / 128, BNQ / 128), 256, GEMM_SMEM>>>(
        aohi, aolo, woT, out, nullptr, nullptr, 1.0f, QD_, INNER, bo);
}

// round 15
// speedup vs baseline: 2.4654x; 1.7401x over previous
#include <cuda_runtime.h>
#include <cuda_fp16.h>
#include <cstdint>
#include <cstddef>

// Problem constants
#define B_    4
#define N_    4096
#define M_    1024
#define QD_   1024
#define CD_   768
#define H_    16
#define D_    64
#define INNER 1024
#define BNQ   (B_ * N_)   // 16384 query rows
#define BMC   (B_ * M_)   // 4096 context rows

// ---------------------------------------------------------------------------
// Static device scratch (all single fp16, fp32 accumulate in MMA)
// ---------------------------------------------------------------------------
__device__ __half g_Q [BNQ * INNER];
__device__ __half g_K [BMC * INNER];
__device__ __half g_V [BMC * INNER];
__device__ __half g_x [BNQ * QD_];
__device__ __half g_c [BMC * CD_];
__device__ __half g_WqT[INNER * QD_];          // weights transposed [N,K]
__device__ __half g_WkT[INNER * CD_];
__device__ __half g_WvT[INNER * CD_];
__device__ __half g_WoT[QD_ * INNER];
__device__ __half g_AO[BNQ * INNER];

// ---------------------------------------------------------------------------
// PTX helpers
// ---------------------------------------------------------------------------
__device__ __forceinline__ uint32_t smem_u32(const void* p) {
    uint32_t a;
    asm("{ .reg .u64 t; cvta.to.shared.u64 t, %1; cvt.u32.u64 %0, t; }"
        : "=r"(a) : "l"(p));
    return a;
}

__device__ __forceinline__ void cp_async16(uint32_t dst, const void* src) {
    asm volatile("cp.async.cg.shared.global [%0], [%1], 16;"
                 :: "r"(dst), "l"(src) : "memory");
}
#define CP_COMMIT() asm volatile("cp.async.commit_group;" ::: "memory")
#define CP_WAIT(n)  asm volatile("cp.async.wait_group %0;" :: "n"(n) : "memory")

__device__ __forceinline__ void ldmatrix_x4(uint32_t& r0, uint32_t& r1,
                                            uint32_t& r2, uint32_t& r3, uint32_t a) {
    asm volatile("ldmatrix.sync.aligned.m8n8.x4.shared.b16 {%0,%1,%2,%3}, [%4];"
                 : "=r"(r0), "=r"(r1), "=r"(r2), "=r"(r3) : "r"(a));
}

__device__ __forceinline__ void ldmatrix_x4_t(uint32_t& r0, uint32_t& r1,
                                              uint32_t& r2, uint32_t& r3, uint32_t a) {
    asm volatile("ldmatrix.sync.aligned.m8n8.x4.trans.shared.b16 {%0,%1,%2,%3}, [%4];"
                 : "=r"(r0), "=r"(r1), "=r"(r2), "=r"(r3) : "r"(a));
}

// fp16 x fp16 -> fp32 accumulate
__device__ __forceinline__ void mma16816(float* d, const uint32_t* a,
                                         const uint32_t* b) {
    asm volatile(
        "mma.sync.aligned.m16n8k16.row.col.f32.f16.f16.f32 "
        "{%0,%1,%2,%3}, {%4,%5,%6,%7}, {%8,%9}, {%0,%1,%2,%3};"
        : "+f"(d[0]), "+f"(d[1]), "+f"(d[2]), "+f"(d[3])
        : "r"(a[0]), "r"(a[1]), "r"(a[2]), "r"(a[3]), "r"(b[0]), "r"(b[1]));
}

__device__ __forceinline__ uint32_t packh2(float v0, float v1) {
    __half2 h = __floats2half2_rn(v0, v1);
    return *reinterpret_cast<uint32_t*>(&h);
}

// ---------------------------------------------------------------------------
// Conversion kernels
// ---------------------------------------------------------------------------
__global__ void cvt_h_kernel(const float* __restrict__ in,
                             __half* __restrict__ out, int n4)
{
    int i = blockIdx.x * blockDim.x + threadIdx.x;
    if (i >= n4) return;
    float4 v = reinterpret_cast<const float4*>(in)[i];
    reinterpret_cast<uint32_t*>(out)[i * 2 + 0] = packh2(v.x, v.y);
    reinterpret_cast<uint32_t*>(out)[i * 2 + 1] = packh2(v.z, v.w);
}

// W [K,N] row-major  ->  T [N,K] single fp16
__global__ void transpose_cvt_kernel(const float* __restrict__ W,
                                     __half* __restrict__ T, int K, int N)
{
    __shared__ float t[32][33];
    int tx = threadIdx.x, ty = threadIdx.y;          // 32 x 8
    int n0 = blockIdx.x * 32, k0 = blockIdx.y * 32;
    #pragma unroll
    for (int j = 0; j < 4; ++j)
        t[ty + j * 8][tx] = W[(size_t)(k0 + ty + j * 8) * N + n0 + tx];
    __syncthreads();
    #pragma unroll
    for (int j = 0; j < 4; ++j) {
        float v = t[tx][ty + j * 8];
        int n = n0 + ty + j * 8, k = k0 + tx;
        T[(size_t)n * K + k] = __float2half_rn(v);
    }
}

// ---------------------------------------------------------------------------
// fp16 GEMM: C = A @ B^T, single-operand (1 MMA per k16 tile).
// BK=32, SA_G=40 halfs -> 2 tensors x 10240 B = 20480/stage, 2 stages
// = 40960 B/CTA. 256 threads, 8 warps 2x4, warp tile 64x32.
// OUTMODE: 1 = fp16 (scale folded), 2 = fp32 + bias
// ---------------------------------------------------------------------------
#define SA_G       40
#define TILE_G     (128 * SA_G * 2)          // 10240 B
#define OFF_A      0
#define OFF_B      (TILE_G)
#define BUF_G      (2 * TILE_G)              // 20480 per stage
#define GEMM_SMEM  (2 * BUF_G)               // 40960

template <int OUTMODE>
__global__ __launch_bounds__(256, 2) void mma_gemm_kernel(
    const __half* __restrict__ As, const __half* __restrict__ Bs,
    float* __restrict__ C, __half* __restrict__ Ch,
    float scale, int Ndim, int Kdim, const float* __restrict__ bias)
{
    extern __shared__ __align__(128) char smem[];
    const uint32_t sb = smem_u32(smem);
    const int tid = threadIdx.x, wid = tid >> 5, l = tid & 31;
    const int warp_m = wid >> 2, warp_n = wid & 3;
    const int brow = blockIdx.y * 128, bcol = blockIdx.x * 128;

    const int a_row = warp_m * 64 + (l & 7) + ((l >> 3) & 1) * 8;
    const int a_col = ((l >> 4) & 1) * 8;
    const int b_row = warp_n * 32 + (l & 7) + ((l >> 4) & 1) * 8;
    const int b_col = ((l >> 3) & 1) * 8;
    const uint32_t aOff = (uint32_t)(a_row * SA_G + a_col) * 2;
    const uint32_t bOff = (uint32_t)(b_row * SA_G + b_col) * 2;

    float acc[4][4][4];
    #pragma unroll
    for (int im = 0; im < 4; ++im)
        #pragma unroll
        for (int j = 0; j < 4; ++j)
            #pragma unroll
            for (int q = 0; q < 4; ++q) acc[im][j][q] = 0.f;

    const int nch = Kdim >> 5;    // BK = 32

    auto stage = [&](int ch, int bb) {
        const int k0 = ch << 5;
        const uint32_t base = sb + (uint32_t)bb * BUF_G;
        #pragma unroll
        for (int i = 0; i < 2; ++i) {
            int s = tid + i * 256;           // 0..511 per tensor
            int r = s >> 2, c = s & 3;       // row, 16B chunk
            uint32_t so = (uint32_t)(r * (SA_G * 2) + c * 16);
            size_t ga = (size_t)(brow + r) * Kdim + k0 + c * 8;
            size_t gb = (size_t)(bcol + r) * Kdim + k0 + c * 8;
            cp_async16(base + OFF_A + so, As + ga);
            cp_async16(base + OFF_B + so, Bs + gb);
        }
        CP_COMMIT();
    };

    stage(0, 0);

    for (int ch = 0; ch < nch; ++ch) {
        CP_WAIT(0);
        __syncthreads();
        if (ch + 1 < nch) stage(ch + 1, (ch + 1) & 1);

        const uint32_t base = sb + (uint32_t)(ch & 1) * BUF_G;
        #pragma unroll
        for (int ks = 0; ks < 2; ++ks) {
            uint32_t bf[4][2];
            #pragma unroll
            for (int in16 = 0; in16 < 2; ++in16) {
                uint32_t bo = bOff + (uint32_t)(in16 * 16 * SA_G + ks * 16) * 2;
                ldmatrix_x4(bf[in16 * 2][0], bf[in16 * 2][1],
                            bf[in16 * 2 + 1][0], bf[in16 * 2 + 1][1],
                            base + OFF_B + bo);
            }
            #pragma unroll
            for (int im = 0; im < 4; ++im) {
                uint32_t af[4];
                uint32_t ao = aOff + (uint32_t)(im * 16 * SA_G + ks * 16) * 2;
                ldmatrix_x4(af[0], af[1], af[2], af[3], base + OFF_A + ao);
                #pragma unroll
                for (int j = 0; j < 4; ++j)
                    mma16816(acc[im][j], af, bf[j]);
            }
        }
    }

    #pragma unroll
    for (int im = 0; im < 4; ++im) {
        int row = brow + warp_m * 64 + im * 16 + (l >> 2);
        #pragma unroll
        for (int j = 0; j < 4; ++j) {
            int col = bcol + warp_n * 32 + j * 8 + (l & 3) * 2;
            float v0 = acc[im][j][0] * scale, v1 = acc[im][j][1] * scale;
            float v2 = acc[im][j][2] * scale, v3 = acc[im][j][3] * scale;
            size_t o0 = (size_t)row * Ndim + col;
            size_t o1 = (size_t)(row + 8) * Ndim + col;
            if (OUTMODE == 1) {
                *reinterpret_cast<uint32_t*>(Ch + o0) = packh2(v0, v1);
                *reinterpret_cast<uint32_t*>(Ch + o1) = packh2(v2, v3);
            } else {
                float2 w0 = {v0, v1}, w1 = {v2, v3};
                if (bias) {
                    float2 bv = *reinterpret_cast<const float2*>(bias + col);
                    w0.x += bv.x; w0.y += bv.y; w1.x += bv.x; w1.y += bv.y;
                }
                *reinterpret_cast<float2*>(C + o0) = w0;
                *reinterpret_cast<float2*>(C + o1) = w1;
            }
        }
    }
}

// ---------------------------------------------------------------------------
// FA2 attention, pure fp16 operands (fp32 accum). 1 MMA per k16 product.
// CTA = (b, h, 128 q rows); 8 warps x 16 rows; kv tile = 64, 2-stage pipeline.
// smem/stage: K | V, each 64 x 72 halfs (9216 B) -> 18432/stage, 36864 total.
// ---------------------------------------------------------------------------
#define SA_       72
#define AT_STG    18432
#define AT_SMEM   (2 * AT_STG)
#define AT_V      9216

__global__ __launch_bounds__(256) void attn_mma_kernel(
    const __half* __restrict__ Qs, const __half* __restrict__ Ks,
    const __half* __restrict__ Vs, __half* __restrict__ AO)
{
    extern __shared__ __align__(128) char smem[];
    const uint32_t sb = smem_u32(smem);
    const int tid = threadIdx.x, wid = tid >> 5, l = tid & 31;
    const int b = blockIdx.z, h = blockIdx.y;
    const int q0 = blockIdx.x * 128;
    const size_t qrow0 = (size_t)(b * N_ + q0);
    const size_t krow0 = (size_t)(b * M_);
    const int hc = h * 64;

    // ---- Stage Q tile (128 x 64) into stage-0 region, build A frags
    #pragma unroll
    for (int i = 0; i < 4; ++i) {
        int s = tid + i * 256;               // 0..1023
        int r = s >> 3, c = s & 7;
        uint32_t so = (uint32_t)(r * 144 + c * 16);
        size_t g = (qrow0 + r) * INNER + hc + c * 8;
        cp_async16(sb + so, Qs + g);
    }
    CP_COMMIT(); CP_WAIT(0);
    __syncthreads();

    uint32_t qf[4][4];
    {
        int ar = wid * 16 + (l & 7) + ((l >> 3) & 1) * 8;
        int ac = ((l >> 4) & 1) * 8;
        #pragma unroll
        for (int ks = 0; ks < 4; ++ks) {
            uint32_t ad = sb + (uint32_t)(ar * SA_ + ac + ks * 16) * 2;
            ldmatrix_x4(qf[ks][0], qf[ks][1], qf[ks][2], qf[ks][3], ad);
        }
    }
    __syncthreads();

    float o[8][4];
    #pragma unroll
    for (int j = 0; j < 8; ++j)
        #pragma unroll
        for (int q = 0; q < 4; ++q) o[j][q] = 0.f;
    float m0 = -1e30f, m1 = -1e30f, lp0 = 0.f, lp1 = 0.f;

    auto stageKV = [&](int t, int bb) {
        const uint32_t base = sb + (uint32_t)bb * AT_STG;
        const int kv0 = t * 64;
        #pragma unroll
        for (int i = 0; i < 2; ++i) {
            int s = tid + i * 256;           // 0..511
            int r = s >> 3, c = s & 7;
            uint32_t so = (uint32_t)(r * 144 + c * 16);
            size_t g = (krow0 + kv0 + r) * INNER + hc + c * 8;
            cp_async16(base + so,        Ks + g);
            cp_async16(base + AT_V + so, Vs + g);
        }
        CP_COMMIT();
    };

    stageKV(0, 0);

    const int nr  = (l & 7) + ((l >> 4) & 1) * 8;
    const int kc8 = ((l >> 3) & 1) * 8;
    const int vg  = l >> 3, vi = l & 7;
    const int NT  = M_ / 64;

    for (int t = 0; t < NT; ++t) {
        CP_WAIT(0);
        __syncthreads();
        if (t + 1 < NT) stageKV(t + 1, (t + 1) & 1);
        const uint32_t kb = sb + (uint32_t)(t & 1) * AT_STG;

        // ---- S = Q K^T
        float s[8][4];
        #pragma unroll
        for (int j = 0; j < 8; ++j)
            #pragma unroll
            for (int q = 0; q < 4; ++q) s[j][q] = 0.f;

        #pragma unroll
        for (int ks = 0; ks < 4; ++ks) {
            #pragma unroll
            for (int jn = 0; jn < 4; ++jn) {
                uint32_t ad = kb + (uint32_t)((jn * 16 + nr) * SA_ + ks * 16 + kc8) * 2;
                uint32_t k0, k1, k2, k3;
                ldmatrix_x4(k0, k1, k2, k3, ad);
                uint32_t b0[2] = {k0, k1}, b1[2] = {k2, k3};
                mma16816(s[2 * jn],     qf[ks], b0);
                mma16816(s[2 * jn + 1], qf[ks], b1);
            }
        }

        // ---- online softmax
        float mx0 = -1e30f, mx1 = -1e30f;
        #pragma unroll
        for (int j = 0; j < 8; ++j) {
            mx0 = fmaxf(mx0, fmaxf(s[j][0], s[j][1]));
            mx1 = fmaxf(mx1, fmaxf(s[j][2], s[j][3]));
        }
        mx0 = fmaxf(mx0, __shfl_xor_sync(0xffffffffu, mx0, 1));
        mx0 = fmaxf(mx0, __shfl_xor_sync(0xffffffffu, mx0, 2));
        mx1 = fmaxf(mx1, __shfl_xor_sync(0xffffffffu, mx1, 1));
        mx1 = fmaxf(mx1, __shfl_xor_sync(0xffffffffu, mx1, 2));

        float nm0 = fmaxf(m0, mx0), nm1 = fmaxf(m1, mx1);
        float al0 = __expf(m0 - nm0), al1 = __expf(m1 - nm1);
        m0 = nm0; m1 = nm1;

        float add0 = 0.f, add1 = 0.f;
        #pragma unroll
        for (int j = 0; j < 8; ++j) {
            s[j][0] = __expf(s[j][0] - nm0);
            s[j][1] = __expf(s[j][1] - nm0);
            s[j][2] = __expf(s[j][2] - nm1);
            s[j][3] = __expf(s[j][3] - nm1);
            add0 += s[j][0] + s[j][1];
            add1 += s[j][2] + s[j][3];
        }
        lp0 = lp0 * al0 + add0;
        lp1 = lp1 * al1 + add1;
        #pragma unroll
        for (int j = 0; j < 8; ++j) {
            o[j][0] *= al0; o[j][1] *= al0;
            o[j][2] *= al1; o[j][3] *= al1;
        }

        // ---- AV, P packed fp16 in-registers
        #pragma unroll
        for (int t2 = 0; t2 < 4; ++t2) {
            uint32_t pa[4];
            pa[0] = packh2(s[2 * t2][0],     s[2 * t2][1]);
            pa[1] = packh2(s[2 * t2][2],     s[2 * t2][3]);
            pa[2] = packh2(s[2 * t2 + 1][0], s[2 * t2 + 1][1]);
            pa[3] = packh2(s[2 * t2 + 1][2], s[2 * t2 + 1][3]);

            #pragma unroll
            for (int jn = 0; jn < 4; ++jn) {
                uint32_t ad = kb + AT_V +
                    (uint32_t)((t2 * 16 + (vg & 1) * 8 + vi) * SA_ +
                               jn * 16 + (vg >> 1) * 8) * 2;
                uint32_t v0, v1, v2, v3;
                ldmatrix_x4_t(v0, v1, v2, v3, ad);
                uint32_t b0[2] = {v0, v1}, b1[2] = {v2, v3};
                mma16816(o[2 * jn],     pa, b0);
                mma16816(o[2 * jn + 1], pa, b1);
            }
        }
    }

    // ---- normalize + write fp16
    lp0 += __shfl_xor_sync(0xffffffffu, lp0, 1);
    lp0 += __shfl_xor_sync(0xffffffffu, lp0, 2);
    lp1 += __shfl_xor_sync(0xffffffffu, lp1, 1);
    lp1 += __shfl_xor_sync(0xffffffffu, lp1, 2);
    float inv0 = 1.f / lp0, inv1 = 1.f / lp1;

    size_t r0g = (qrow0 + wid * 16 + (l >> 2)) * INNER + hc;
    size_t r1g = r0g + (size_t)8 * INNER;
    #pragma unroll
    for (int j = 0; j < 8; ++j) {
        int c = j * 8 + (l & 3) * 2;
        *reinterpret_cast<uint32_t*>(AO + r0g + c) =
            packh2(o[j][0] * inv0, o[j][1] * inv0);
        *reinterpret_cast<uint32_t*>(AO + r1g + c) =
            packh2(o[j][2] * inv1, o[j][3] * inv1);
    }
}

// ---------------------------------------------------------------------------
// Launch
// ---------------------------------------------------------------------------
extern "C" void kernel_launch(void* const* d_in, const int* in_sizes, int n_in,
                              void* d_out, int out_size)
{
    const float* x   = (const float*)d_in[0];
    const float* ctx = (const float*)d_in[1];
    const float* Wq  = (const float*)d_in[2];
    const float* Wk  = (const float*)d_in[3];
    const float* Wv  = (const float*)d_in[4];
    const float* Wo  = (const float*)d_in[5];
    const float* bo  = (const float*)d_in[6];
    float* out = (float*)d_out;

    cudaFuncSetAttribute(mma_gemm_kernel<1>,
                         cudaFuncAttributeMaxDynamicSharedMemorySize, GEMM_SMEM);
    cudaFuncSetAttribute(mma_gemm_kernel<2>,
                         cudaFuncAttributeMaxDynamicSharedMemorySize, GEMM_SMEM);
    cudaFuncSetAttribute(attn_mma_kernel,
                         cudaFuncAttributeMaxDynamicSharedMemorySize, AT_SMEM);

    __half *qs, *ks, *vs, *xs, *cs, *ao, *wqT, *wkT, *wvT, *woT;
    cudaGetSymbolAddress((void**)&qs, g_Q);    cudaGetSymbolAddress((void**)&ks, g_K);
    cudaGetSymbolAddress((void**)&vs, g_V);    cudaGetSymbolAddress((void**)&xs, g_x);
    cudaGetSymbolAddress((void**)&cs, g_c);    cudaGetSymbolAddress((void**)&ao, g_AO);
    cudaGetSymbolAddress((void**)&wqT, g_WqT); cudaGetSymbolAddress((void**)&wkT, g_WkT);
    cudaGetSymbolAddress((void**)&wvT, g_WvT); cudaGetSymbolAddress((void**)&woT, g_WoT);

    // 1. Convert inputs / transpose-convert weights to fp16
    {
        int n4 = (BNQ * QD_) / 4;
        cvt_h_kernel<<<n4 / 256, 256>>>(x, xs, n4);
        n4 = (BMC * CD_) / 4;
        cvt_h_kernel<<<n4 / 256, 256>>>(ctx, cs, n4);
    }
    transpose_cvt_kernel<<<dim3(INNER / 32, QD_ / 32), dim3(32, 8)>>>(Wq, wqT, QD_, INNER);
    transpose_cvt_kernel<<<dim3(INNER / 32, CD_ / 32), dim3(32, 8)>>>(Wk, wkT, CD_, INNER);
    transpose_cvt_kernel<<<dim3(INNER / 32, CD_ / 32), dim3(32, 8)>>>(Wv, wvT, CD_, INNER);
    transpose_cvt_kernel<<<dim3(QD_ / 32, INNER / 32), dim3(32, 8)>>>(Wo, woT, INNER, QD_);

    // 2. Projections (Q with softmax scale folded)
    mma_gemm_kernel<1><<<dim3(INNER / 128, BNQ / 128), 256, GEMM_SMEM>>>(
        xs, wqT, nullptr, qs, 0.125f, INNER, QD_, nullptr);
    mma_gemm_kernel<1><<<dim3(INNER / 128, BMC / 128), 256, GEMM_SMEM>>>(
        cs, wkT, nullptr, ks, 1.0f, INNER, CD_, nullptr);
    mma_gemm_kernel<1><<<dim3(INNER / 128, BMC / 128), 256, GEMM_SMEM>>>(
        cs, wvT, nullptr, vs, 1.0f, INNER, CD_, nullptr);

    // 3. Attention (fp16 FA2)
    attn_mma_kernel<<<dim3(N_ / 128, H_, B_), 256, AT_SMEM>>>(qs, ks, vs, ao);

    // 4. Output projection + bias -> d_out (fp32)
    mma_gemm_kernel<2><<<dim3(QD_ / 128, BNQ / 128), 256, GEMM_SMEM>>>(
        ao, woT, out, nullptr, 1.0f, QD_, INNER, bo);
}